// round 2
// baseline (speedup 1.0000x reference)
#include <cuda_runtime.h>
#include <cuda_bf16.h>

#define B 2
#define S 2048
#define HID 2048
#define H 16
#define KVH 4
#define D 128
#define GROUPS (H / KVH)
#define MROWS (B * S)          // 4096

// ---------------- scratch (no allocations allowed) ----------------
__device__ float g_q[MROWS * H * D];     // [b,s,h,d]
__device__ float g_k[MROWS * KVH * D];   // [b,s,kvh,d]
__device__ float g_v[MROWS * KVH * D];
__device__ float g_o[MROWS * H * D];     // attention output [b,s,h,d]

// ---------------- SGEMM: C[M,N] = A[M,K] @ W[K,N], all row-major ----------------
#define BM 128
#define BN 128
#define BK 8
#define TM 8
#define TN 8

__global__ __launch_bounds__(256) void sgemm_kernel(
    const float* __restrict__ A, const float* __restrict__ W,
    float* __restrict__ C, int M, int N, int K)
{
    __shared__ float As[BK][BM];
    __shared__ float Bs[BK][BN];
    const int tid = threadIdx.x;
    const int tr = tid / 16, tc = tid % 16;
    const int m0 = blockIdx.y * BM, n0 = blockIdx.x * BN;

    const int a_row = tid / 2;            // 0..127
    const int a_col = (tid % 2) * 4;      // 0 or 4
    const int b_row = tid / 32;           // 0..7
    const int b_col = (tid % 32) * 4;     // 0..124

    float acc[TM][TN] = {};
    float ar[TM], br[TN];

    for (int k0 = 0; k0 < K; k0 += BK) {
        float4 av = *reinterpret_cast<const float4*>(&A[(m0 + a_row) * K + k0 + a_col]);
        As[a_col + 0][a_row] = av.x;
        As[a_col + 1][a_row] = av.y;
        As[a_col + 2][a_row] = av.z;
        As[a_col + 3][a_row] = av.w;
        float4 bv = *reinterpret_cast<const float4*>(&W[(k0 + b_row) * N + n0 + b_col]);
        *reinterpret_cast<float4*>(&Bs[b_row][b_col]) = bv;
        __syncthreads();
#pragma unroll
        for (int k = 0; k < BK; k++) {
#pragma unroll
            for (int i = 0; i < TM; i += 4)
                *reinterpret_cast<float4*>(&ar[i]) =
                    *reinterpret_cast<const float4*>(&As[k][tr * TM + i]);
#pragma unroll
            for (int j = 0; j < TN; j += 4)
                *reinterpret_cast<float4*>(&br[j]) =
                    *reinterpret_cast<const float4*>(&Bs[k][tc * TN + j]);
#pragma unroll
            for (int i = 0; i < TM; i++)
#pragma unroll
                for (int j = 0; j < TN; j++)
                    acc[i][j] += ar[i] * br[j];
        }
        __syncthreads();
    }
#pragma unroll
    for (int i = 0; i < TM; i++) {
        int m = m0 + tr * TM + i;
#pragma unroll
        for (int j = 0; j < TN; j += 4) {
            int n = n0 + tc * TN + j;
            float4 v = make_float4(acc[i][j], acc[i][j + 1], acc[i][j + 2], acc[i][j + 3]);
            *reinterpret_cast<float4*>(&C[m * N + n]) = v;
        }
    }
}

// ---------------- RoPE on q and k (in place) ----------------
__global__ void rope_kernel(float* __restrict__ q, float* __restrict__ k,
                            const float* __restrict__ fc)
{
    const int total_q = MROWS * H * (D / 2);
    const int total_k = MROWS * KVH * (D / 2);
    int idx = blockIdx.x * blockDim.x + threadIdx.x;
    if (idx < total_q) {
        int i  = idx % (D / 2);
        int hd = idx / (D / 2);        // bs*H + h
        int bs = hd / H;
        int s  = bs % S;
        float c  = fc[(s * (D / 2) + i) * 2 + 0];
        float sn = fc[(s * (D / 2) + i) * 2 + 1];
        float* p = q + hd * D + 2 * i;
        float x0 = p[0], x1 = p[1];
        p[0] = x0 * c - x1 * sn;
        p[1] = x0 * sn + x1 * c;
    } else if (idx < total_q + total_k) {
        int pr = idx - total_q;
        int i  = pr % (D / 2);
        int hd = pr / (D / 2);         // bs*KVH + kvh
        int bs = hd / KVH;
        int s  = bs % S;
        float c  = fc[(s * (D / 2) + i) * 2 + 0];
        float sn = fc[(s * (D / 2) + i) * 2 + 1];
        float* p = k + hd * D + 2 * i;
        float x0 = p[0], x1 = p[1];
        p[0] = x0 * c - x1 * sn;
        p[1] = x0 * sn + x1 * c;
    }
}

// ---------------- flash attention, fp32, causal, GQA ----------------
#define AB_M 64
#define AB_N 64
#define PS_STRIDE 65

__global__ __launch_bounds__(256) void attn_kernel(
    const float* __restrict__ Q, const float* __restrict__ Kg,
    const float* __restrict__ Vg, float* __restrict__ O)
{
    extern __shared__ float sm[];
    float* Qs = sm;                         // [128][64] transposed
    float* Ks = Qs + D * AB_M;              // [128][64] transposed
    float* Vs = Ks + D * AB_N;              // [64][128]
    float* Ps = Vs + AB_N * D;              // [64][65]
    float* row_m = Ps + AB_M * PS_STRIDE;   // [64]
    float* row_l = row_m + AB_M;            // [64]
    float* row_scale = row_l + AB_M;        // [64]

    const int tid = threadIdx.x;
    const int bxq = blockIdx.x;
    const int h   = blockIdx.y;
    const int b   = blockIdx.z;
    const int kvh = h / GROUPS;
    const int q0  = bxq * AB_M;
    const float scale = 0.08838834764831845f; // 1/sqrt(128)

    // load Q tile transposed
    {
        int m  = tid / 4;
        int c4 = (tid % 4) * 4;
        const float* qrow = Q + ((b * S + q0 + m) * H + h) * D;
#pragma unroll
        for (int j = 0; j < 8; j++) {
            int d = c4 + j * 16;
            float4 v = *reinterpret_cast<const float4*>(qrow + d);
            Qs[(d + 0) * AB_M + m] = v.x;
            Qs[(d + 1) * AB_M + m] = v.y;
            Qs[(d + 2) * AB_M + m] = v.z;
            Qs[(d + 3) * AB_M + m] = v.w;
        }
    }
    if (tid < AB_M) { row_m[tid] = -1e30f; row_l[tid] = 0.f; }

    const int tr = tid / 16, tc = tid % 16;
    float o_acc[4][8] = {};

    const int ntiles = bxq + 1;
    for (int t = 0; t < ntiles; t++) {
        const int kv0 = t * AB_N;
        __syncthreads();
        // load K (transposed) and V tiles
        {
            int n  = tid / 4;
            int c4 = (tid % 4) * 4;
            const float* krow = Kg + ((b * S + kv0 + n) * KVH + kvh) * D;
            const float* vrow = Vg + ((b * S + kv0 + n) * KVH + kvh) * D;
#pragma unroll
            for (int j = 0; j < 8; j++) {
                int d = c4 + j * 16;
                float4 kv = *reinterpret_cast<const float4*>(krow + d);
                Ks[(d + 0) * AB_N + n] = kv.x;
                Ks[(d + 1) * AB_N + n] = kv.y;
                Ks[(d + 2) * AB_N + n] = kv.z;
                Ks[(d + 3) * AB_N + n] = kv.w;
                float4 vv = *reinterpret_cast<const float4*>(vrow + d);
                *reinterpret_cast<float4*>(&Vs[n * D + d]) = vv;
            }
        }
        __syncthreads();

        // S = (Q K^T) * scale, masked
        float s_acc[4][4] = {};
#pragma unroll 4
        for (int d = 0; d < D; d++) {
            float a[4], bb[4];
            *reinterpret_cast<float4*>(a)  = *reinterpret_cast<const float4*>(&Qs[d * AB_M + tr * 4]);
            *reinterpret_cast<float4*>(bb) = *reinterpret_cast<const float4*>(&Ks[d * AB_N + tc * 4]);
#pragma unroll
            for (int i = 0; i < 4; i++)
#pragma unroll
                for (int j = 0; j < 4; j++)
                    s_acc[i][j] += a[i] * bb[j];
        }
#pragma unroll
        for (int i = 0; i < 4; i++) {
            int m = tr * 4 + i, qg = q0 + m;
#pragma unroll
            for (int j = 0; j < 4; j++) {
                int n = tc * 4 + j, kg = kv0 + n;
                float sv = s_acc[i][j] * scale;
                if (kg > qg) sv = -1e30f;
                Ps[m * PS_STRIDE + n] = sv;
            }
        }
        __syncthreads();

        // online softmax row update
        if (tid < AB_M) {
            int m = tid;
            float* pr = Ps + m * PS_STRIDE;
            float rmax = -1e30f;
#pragma unroll 8
            for (int n = 0; n < AB_N; n++) rmax = fmaxf(rmax, pr[n]);
            float old_m = row_m[m];
            float new_m = fmaxf(old_m, rmax);
            float f = __expf(old_m - new_m);
            float rsum = 0.f;
#pragma unroll 8
            for (int n = 0; n < AB_N; n++) {
                float p = __expf(pr[n] - new_m);
                pr[n] = p;
                rsum += p;
            }
            row_m[m] = new_m;
            row_l[m] = row_l[m] * f + rsum;
            row_scale[m] = f;
        }
        __syncthreads();

        // rescale O, accumulate P @ V
        {
            float fs[4];
#pragma unroll
            for (int i = 0; i < 4; i++) fs[i] = row_scale[tr * 4 + i];
#pragma unroll
            for (int i = 0; i < 4; i++)
#pragma unroll
                for (int j = 0; j < 8; j++)
                    o_acc[i][j] *= fs[i];
#pragma unroll 2
            for (int n = 0; n < AB_N; n++) {
                float p[4];
#pragma unroll
                for (int i = 0; i < 4; i++) p[i] = Ps[(tr * 4 + i) * PS_STRIDE + n];
                float v[8];
                *reinterpret_cast<float4*>(v)     = *reinterpret_cast<const float4*>(&Vs[n * D + tc * 8]);
                *reinterpret_cast<float4*>(v + 4) = *reinterpret_cast<const float4*>(&Vs[n * D + tc * 8 + 4]);
#pragma unroll
                for (int i = 0; i < 4; i++)
#pragma unroll
                    for (int j = 0; j < 8; j++)
                        o_acc[i][j] += p[i] * v[j];
            }
        }
    }

    // epilogue: normalize and store [b, s, h, d]
#pragma unroll
    for (int i = 0; i < 4; i++) {
        int m = tr * 4 + i;
        float inv_l = 1.0f / row_l[m];
        float* orow = O + ((b * S + q0 + m) * H + h) * D + tc * 8;
#pragma unroll
        for (int j = 0; j < 8; j += 4) {
            float4 v = make_float4(o_acc[i][j] * inv_l, o_acc[i][j + 1] * inv_l,
                                   o_acc[i][j + 2] * inv_l, o_acc[i][j + 3] * inv_l);
            *reinterpret_cast<float4*>(orow + j) = v;
        }
    }
}

// ---------------- host ----------------
extern "C" void kernel_launch(void* const* d_in, const int* in_sizes, int n_in,
                              void* d_out, int out_size)
{
    const float* x  = (const float*)d_in[0];
    const float* fc = (const float*)d_in[1];
    const float* wq = (const float*)d_in[2];
    const float* wk = (const float*)d_in[3];
    const float* wv = (const float*)d_in[4];
    const float* wo = (const float*)d_in[5];
    float* out = (float*)d_out;

    float *pq, *pk, *pv, *po;
    cudaGetSymbolAddress((void**)&pq, g_q);
    cudaGetSymbolAddress((void**)&pk, g_k);
    cudaGetSymbolAddress((void**)&pv, g_v);
    cudaGetSymbolAddress((void**)&po, g_o);

    // QKV projections
    {
        dim3 blk(256);
        dim3 gq(H * D / BN, MROWS / BM);     // (16, 32)
        dim3 gkv(KVH * D / BN, MROWS / BM);  // (4, 32)
        sgemm_kernel<<<gq, blk>>>(x, wq, pq, MROWS, H * D, HID);
        sgemm_kernel<<<gkv, blk>>>(x, wk, pk, MROWS, KVH * D, HID);
        sgemm_kernel<<<gkv, blk>>>(x, wv, pv, MROWS, KVH * D, HID);
    }

    // RoPE
    {
        int total = MROWS * H * (D / 2) + MROWS * KVH * (D / 2);
        int blocks = (total + 255) / 256;
        rope_kernel<<<blocks, 256>>>(pq, pk, fc);
    }

    // attention
    {
        size_t smem = (size_t)(D * AB_M + D * AB_N + AB_N * D +
                               AB_M * PS_STRIDE + 3 * AB_M) * sizeof(float);
        cudaFuncSetAttribute(attn_kernel, cudaFuncAttributeMaxDynamicSharedMemorySize,
                             (int)smem);
        dim3 grid(S / AB_M, H, B);
        attn_kernel<<<grid, 256, smem>>>(pq, pk, pv, po);
    }

    // output projection
    {
        dim3 blk(256);
        dim3 g(HID / BN, MROWS / BM);        // (16, 32)
        sgemm_kernel<<<g, blk>>>(po, wo, out, MROWS, HID, HID);
    }
}

// round 4
// speedup vs baseline: 1.6007x; 1.6007x over previous
#include <cuda_runtime.h>
#include <cuda_bf16.h>
#include <cstdint>

#define B 2
#define S 2048
#define HID 2048
#define H 16
#define KVH 4
#define D 128
#define GROUPS (H / KVH)
#define MROWS (B * S)          // 4096
#define ND_Q (H * D)           // 2048
#define ND_KV (KVH * D)        // 512

// ---------------- scratch (no allocations allowed) ----------------
__device__ float g_q[MROWS * H * D];
__device__ float g_k[MROWS * KVH * D];
__device__ float g_v[MROWS * KVH * D];
__device__ float g_o[MROWS * H * D];

__device__ __align__(16) __nv_bfloat16 g_xa_hi[MROWS * HID];
__device__ __align__(16) __nv_bfloat16 g_xa_lo[MROWS * HID];
__device__ __align__(16) __nv_bfloat16 g_oa_hi[MROWS * ND_Q];
__device__ __align__(16) __nv_bfloat16 g_oa_lo[MROWS * ND_Q];
__device__ __align__(16) __nv_bfloat16 g_wqT_hi[ND_Q * HID];
__device__ __align__(16) __nv_bfloat16 g_wqT_lo[ND_Q * HID];
__device__ __align__(16) __nv_bfloat16 g_wkT_hi[ND_KV * HID];
__device__ __align__(16) __nv_bfloat16 g_wkT_lo[ND_KV * HID];
__device__ __align__(16) __nv_bfloat16 g_wvT_hi[ND_KV * HID];
__device__ __align__(16) __nv_bfloat16 g_wvT_lo[ND_KV * HID];
__device__ __align__(16) __nv_bfloat16 g_woT_hi[HID * ND_Q];
__device__ __align__(16) __nv_bfloat16 g_woT_lo[HID * ND_Q];

// ---------------- helpers ----------------
__device__ __forceinline__ uint32_t smem_u32(const void* p) {
    uint32_t a;
    asm("{ .reg .u64 t; cvta.to.shared.u64 t, %1; cvt.u32.u64 %0, t; }" : "=r"(a) : "l"(p));
    return a;
}
__device__ __forceinline__ void cp_async16(uint32_t saddr, const void* gaddr) {
    asm volatile("cp.async.cg.shared.global [%0], [%1], 16;" :: "r"(saddr), "l"(gaddr)
                 : "memory");
}
__device__ __forceinline__ void cp_commit() {
    asm volatile("cp.async.commit_group;" ::: "memory");
}
template <int N>
__device__ __forceinline__ void cp_wait() {
    asm volatile("cp.async.wait_group %0;" :: "n"(N) : "memory");
}
__device__ __forceinline__ void ldsm_x4(uint32_t* r, uint32_t addr) {
    asm volatile("ldmatrix.sync.aligned.m8n8.x4.shared.b16 {%0,%1,%2,%3}, [%4];"
                 : "=r"(r[0]), "=r"(r[1]), "=r"(r[2]), "=r"(r[3]) : "r"(addr));
}
__device__ __forceinline__ void mma_bf16(float* c, const uint32_t* a, const uint32_t* b) {
    asm volatile(
        "mma.sync.aligned.m16n8k16.row.col.f32.bf16.bf16.f32 "
        "{%0,%1,%2,%3}, {%4,%5,%6,%7}, {%8,%9}, {%0,%1,%2,%3};"
        : "+f"(c[0]), "+f"(c[1]), "+f"(c[2]), "+f"(c[3])
        : "r"(a[0]), "r"(a[1]), "r"(a[2]), "r"(a[3]), "r"(b[0]), "r"(b[1]));
}

// ---------------- split fp32 -> (hi, lo) bf16 ----------------
__global__ void split_f32(const float4* __restrict__ src, __nv_bfloat162* __restrict__ hi,
                          __nv_bfloat162* __restrict__ lo, int n4) {
    int i = blockIdx.x * blockDim.x + threadIdx.x;
    if (i >= n4) return;
    float4 v = src[i];
    __nv_bfloat16 h0 = __float2bfloat16(v.x);
    __nv_bfloat16 h1 = __float2bfloat16(v.y);
    __nv_bfloat16 h2 = __float2bfloat16(v.z);
    __nv_bfloat16 h3 = __float2bfloat16(v.w);
    hi[2 * i]     = __halves2bfloat162(h0, h1);
    hi[2 * i + 1] = __halves2bfloat162(h2, h3);
    lo[2 * i]     = __halves2bfloat162(__float2bfloat16(v.x - __bfloat162float(h0)),
                                       __float2bfloat16(v.y - __bfloat162float(h1)));
    lo[2 * i + 1] = __halves2bfloat162(__float2bfloat16(v.z - __bfloat162float(h2)),
                                       __float2bfloat16(v.w - __bfloat162float(h3)));
}

// ---------------- transpose + split: W[K,N] fp32 -> T[N,K] (hi, lo) bf16 ----------------
__global__ void transpose_split(const float* __restrict__ W, __nv_bfloat16* __restrict__ Thi,
                                __nv_bfloat16* __restrict__ Tlo, int K, int N) {
    __shared__ float t[32][33];
    int k0 = blockIdx.y * 32, n0 = blockIdx.x * 32;
    int tx = threadIdx.x, ty = threadIdx.y;
#pragma unroll
    for (int j = 0; j < 4; j++)
        t[ty + j * 8][tx] = W[(size_t)(k0 + ty + j * 8) * N + n0 + tx];
    __syncthreads();
#pragma unroll
    for (int j = 0; j < 4; j++) {
        int n = n0 + ty + j * 8;
        float v = t[tx][ty + j * 8];
        __nv_bfloat16 h = __float2bfloat16(v);
        Thi[(size_t)n * K + k0 + tx] = h;
        Tlo[(size_t)n * K + k0 + tx] = __float2bfloat16(v - __bfloat162float(h));
    }
}

// ---------------- bf16x3 tensor-core GEMM via mma.sync ----------------
// C[M,N] = A[M,K] @ T[N,K]^T ; A,T given as (hi, lo) bf16 pairs.
#define GBM 128
#define GBN 128
#define GBK 32
#define LDT 40                         // smem row stride in bf16 (32 + 8 pad = 80 B)
#define TILE_E (GBM * LDT)             // 5120 elements per tile
#define STAGE_E (4 * TILE_E)           // Ah, Al, Bh, Bl
#define GSM_BYTES (2 * STAGE_E * 2)    // two stages, bf16

__global__ __launch_bounds__(256, 1)
void gemm_tc(const __nv_bfloat16* __restrict__ Ahi, const __nv_bfloat16* __restrict__ Alo,
             const __nv_bfloat16* __restrict__ Bhi, const __nv_bfloat16* __restrict__ Blo,
             float* __restrict__ C, int M, int N, int K)
{
    extern __shared__ __nv_bfloat16 sm[];
    const uint32_t sb = smem_u32(sm);
    const int tid = threadIdx.x;
    const int wid = tid / 32, lane = tid % 32;
    const int warp_m = wid % 4;        // 4 warps over M: 32 rows each
    const int warp_n = wid / 4;        // 2 warps over N: 64 cols each
    const int m0 = blockIdx.y * GBM, n0 = blockIdx.x * GBN;

    // per-thread gmem load coords: 2 rows per tile, 16B per row-part
    const int ld_row = tid / 4;            // 0..63
    const int ld_col = (tid % 4) * 8;      // bf16 offset (0,8,16,24)

    const __nv_bfloat16* pAh = Ahi + (size_t)(m0 + ld_row) * K + ld_col;
    const __nv_bfloat16* pAl = Alo + (size_t)(m0 + ld_row) * K + ld_col;
    const __nv_bfloat16* pBh = Bhi + (size_t)(n0 + ld_row) * K + ld_col;
    const __nv_bfloat16* pBl = Blo + (size_t)(n0 + ld_row) * K + ld_col;
    const size_t rstep64 = (size_t)64 * K;

    auto load_chunk = [&](int t, int stg) {
        uint32_t sbase = sb + (uint32_t)(stg * STAGE_E) * 2u;
        uint32_t soff = ((uint32_t)ld_row * LDT + (uint32_t)ld_col) * 2u;
        const int kk = t * GBK;
#pragma unroll
        for (int j = 0; j < 2; j++) {
            uint32_t so = soff + (uint32_t)(j * 64 * LDT) * 2u;
            cp_async16(sbase + 0 * TILE_E * 2 + so, pAh + kk + j * rstep64);
            cp_async16(sbase + 1 * TILE_E * 2 + so, pAl + kk + j * rstep64);
            cp_async16(sbase + 2 * TILE_E * 2 + so, pBh + kk + j * rstep64);
            cp_async16(sbase + 3 * TILE_E * 2 + so, pBl + kk + j * rstep64);
        }
    };

    float acc[2][8][4];
#pragma unroll
    for (int i = 0; i < 2; i++)
#pragma unroll
        for (int j = 0; j < 8; j++)
#pragma unroll
            for (int r = 0; r < 4; r++) acc[i][j][r] = 0.f;

    const int nch = K / GBK;
    load_chunk(0, 0);
    cp_commit();

    for (int t = 0; t < nch; t++) {
        const int stg = t & 1;
        if (t + 1 < nch) {
            load_chunk(t + 1, stg ^ 1);
            cp_commit();
            cp_wait<1>();
        } else {
            cp_wait<0>();
        }
        __syncthreads();

        const uint32_t sbase = sb + (uint32_t)(stg * STAGE_E) * 2u;
#pragma unroll
        for (int ks = 0; ks < 2; ks++) {
            const uint32_t kc = (uint32_t)(ks * 16 + (lane / 16) * 8);
            // A fragments (hi, lo): 2 m-tiles
            uint32_t ah[2][4], al[2][4];
#pragma unroll
            for (int mt = 0; mt < 2; mt++) {
                uint32_t row = (uint32_t)(warp_m * 32 + mt * 16 + (lane % 16));
                uint32_t off = (row * LDT + kc) * 2u;
                ldsm_x4(ah[mt], sbase + 0 * TILE_E * 2 + off);
                ldsm_x4(al[mt], sbase + 1 * TILE_E * 2 + off);
            }
            // B fragments (hi, lo): 8 n-tiles via 4 x4-loads each
            uint32_t bh[8][2], bl[8][2];
#pragma unroll
            for (int ng = 0; ng < 4; ng++) {
                uint32_t row = (uint32_t)(warp_n * 64 + ng * 16 + (lane % 8) +
                                          ((lane / 8) % 2) * 8);
                uint32_t off = (row * LDT + kc) * 2u;
                uint32_t r[4];
                ldsm_x4(r, sbase + 2 * TILE_E * 2 + off);
                bh[2 * ng][0] = r[0]; bh[2 * ng][1] = r[2];
                bh[2 * ng + 1][0] = r[1]; bh[2 * ng + 1][1] = r[3];
                ldsm_x4(r, sbase + 3 * TILE_E * 2 + off);
                bl[2 * ng][0] = r[0]; bl[2 * ng][1] = r[2];
                bl[2 * ng + 1][0] = r[1]; bl[2 * ng + 1][1] = r[3];
            }
#pragma unroll
            for (int mt = 0; mt < 2; mt++)
#pragma unroll
                for (int nt = 0; nt < 8; nt++) {
                    mma_bf16(acc[mt][nt], ah[mt], bh[nt]);
                    mma_bf16(acc[mt][nt], ah[mt], bl[nt]);
                    mma_bf16(acc[mt][nt], al[mt], bh[nt]);
                }
        }
        __syncthreads();
    }

    // epilogue
#pragma unroll
    for (int mt = 0; mt < 2; mt++) {
        int row = m0 + warp_m * 32 + mt * 16 + lane / 4;
#pragma unroll
        for (int nt = 0; nt < 8; nt++) {
            int col = n0 + warp_n * 64 + nt * 8 + (lane % 4) * 2;
            float2 v0 = make_float2(acc[mt][nt][0], acc[mt][nt][1]);
            float2 v1 = make_float2(acc[mt][nt][2], acc[mt][nt][3]);
            *reinterpret_cast<float2*>(&C[(size_t)row * N + col]) = v0;
            *reinterpret_cast<float2*>(&C[(size_t)(row + 8) * N + col]) = v1;
        }
    }
}

// ---------------- RoPE on q and k (in place) ----------------
__global__ void rope_kernel(float* __restrict__ q, float* __restrict__ k,
                            const float* __restrict__ fc)
{
    const int total_q = MROWS * H * (D / 2);
    const int total_k = MROWS * KVH * (D / 2);
    int idx = blockIdx.x * blockDim.x + threadIdx.x;
    if (idx < total_q) {
        int i  = idx % (D / 2);
        int hd = idx / (D / 2);
        int bs = hd / H;
        int s  = bs % S;
        float c  = fc[(s * (D / 2) + i) * 2 + 0];
        float sn = fc[(s * (D / 2) + i) * 2 + 1];
        float* p = q + (size_t)hd * D + 2 * i;
        float x0 = p[0], x1 = p[1];
        p[0] = x0 * c - x1 * sn;
        p[1] = x0 * sn + x1 * c;
    } else if (idx < total_q + total_k) {
        int pr = idx - total_q;
        int i  = pr % (D / 2);
        int hd = pr / (D / 2);
        int bs = hd / KVH;
        int s  = bs % S;
        float c  = fc[(s * (D / 2) + i) * 2 + 0];
        float sn = fc[(s * (D / 2) + i) * 2 + 1];
        float* p = k + (size_t)hd * D + 2 * i;
        float x0 = p[0], x1 = p[1];
        p[0] = x0 * c - x1 * sn;
        p[1] = x0 * sn + x1 * c;
    }
}

// ---------------- flash attention, fp32, causal, GQA ----------------
#define AB_M 64
#define AB_N 64
#define PS_STRIDE 65

__global__ __launch_bounds__(256) void attn_kernel(
    const float* __restrict__ Q, const float* __restrict__ Kg,
    const float* __restrict__ Vg, float* __restrict__ O)
{
    extern __shared__ float smf[];
    float* Qs = smf;
    float* Ks = Qs + D * AB_M;
    float* Vs = Ks + D * AB_N;
    float* Ps = Vs + AB_N * D;
    float* row_m = Ps + AB_M * PS_STRIDE;
    float* row_l = row_m + AB_M;
    float* row_scale = row_l + AB_M;

    const int tid = threadIdx.x;
    const int bxq = blockIdx.x;
    const int h   = blockIdx.y;
    const int b   = blockIdx.z;
    const int kvh = h / GROUPS;
    const int q0  = bxq * AB_M;
    const float scale = 0.08838834764831845f;

    {
        int m  = tid / 4;
        int c4 = (tid % 4) * 4;
        const float* qrow = Q + ((size_t)(b * S + q0 + m) * H + h) * D;
#pragma unroll
        for (int j = 0; j < 8; j++) {
            int d = c4 + j * 16;
            float4 v = *reinterpret_cast<const float4*>(qrow + d);
            Qs[(d + 0) * AB_M + m] = v.x;
            Qs[(d + 1) * AB_M + m] = v.y;
            Qs[(d + 2) * AB_M + m] = v.z;
            Qs[(d + 3) * AB_M + m] = v.w;
        }
    }
    if (tid < AB_M) { row_m[tid] = -1e30f; row_l[tid] = 0.f; }

    const int tr = tid / 16, tc = tid % 16;
    float o_acc[4][8] = {};

    const int ntiles = bxq + 1;
    for (int t = 0; t < ntiles; t++) {
        const int kv0 = t * AB_N;
        __syncthreads();
        {
            int n  = tid / 4;
            int c4 = (tid % 4) * 4;
            const float* krow = Kg + ((size_t)(b * S + kv0 + n) * KVH + kvh) * D;
            const float* vrow = Vg + ((size_t)(b * S + kv0 + n) * KVH + kvh) * D;
#pragma unroll
            for (int j = 0; j < 8; j++) {
                int d = c4 + j * 16;
                float4 kv = *reinterpret_cast<const float4*>(krow + d);
                Ks[(d + 0) * AB_N + n] = kv.x;
                Ks[(d + 1) * AB_N + n] = kv.y;
                Ks[(d + 2) * AB_N + n] = kv.z;
                Ks[(d + 3) * AB_N + n] = kv.w;
                float4 vv = *reinterpret_cast<const float4*>(vrow + d);
                *reinterpret_cast<float4*>(&Vs[n * D + d]) = vv;
            }
        }
        __syncthreads();

        float s_acc[4][4] = {};
#pragma unroll 4
        for (int d = 0; d < D; d++) {
            float a[4], bb[4];
            *reinterpret_cast<float4*>(a)  = *reinterpret_cast<const float4*>(&Qs[d * AB_M + tr * 4]);
            *reinterpret_cast<float4*>(bb) = *reinterpret_cast<const float4*>(&Ks[d * AB_N + tc * 4]);
#pragma unroll
            for (int i = 0; i < 4; i++)
#pragma unroll
                for (int j = 0; j < 4; j++)
                    s_acc[i][j] += a[i] * bb[j];
        }
#pragma unroll
        for (int i = 0; i < 4; i++) {
            int m = tr * 4 + i, qg = q0 + m;
#pragma unroll
            for (int j = 0; j < 4; j++) {
                int n = tc * 4 + j, kg = kv0 + n;
                float sv = s_acc[i][j] * scale;
                if (kg > qg) sv = -1e30f;
                Ps[m * PS_STRIDE + n] = sv;
            }
        }
        __syncthreads();

        if (tid < AB_M) {
            int m = tid;
            float* pr = Ps + m * PS_STRIDE;
            float rmax = -1e30f;
#pragma unroll 8
            for (int n = 0; n < AB_N; n++) rmax = fmaxf(rmax, pr[n]);
            float old_m = row_m[m];
            float new_m = fmaxf(old_m, rmax);
            float f = __expf(old_m - new_m);
            float rsum = 0.f;
#pragma unroll 8
            for (int n = 0; n < AB_N; n++) {
                float p = __expf(pr[n] - new_m);
                pr[n] = p;
                rsum += p;
            }
            row_m[m] = new_m;
            row_l[m] = row_l[m] * f + rsum;
            row_scale[m] = f;
        }
        __syncthreads();

        {
            float fs[4];
#pragma unroll
            for (int i = 0; i < 4; i++) fs[i] = row_scale[tr * 4 + i];
#pragma unroll
            for (int i = 0; i < 4; i++)
#pragma unroll
                for (int j = 0; j < 8; j++)
                    o_acc[i][j] *= fs[i];
#pragma unroll 2
            for (int n = 0; n < AB_N; n++) {
                float p[4];
#pragma unroll
                for (int i = 0; i < 4; i++) p[i] = Ps[(tr * 4 + i) * PS_STRIDE + n];
                float v[8];
                *reinterpret_cast<float4*>(v)     = *reinterpret_cast<const float4*>(&Vs[n * D + tc * 8]);
                *reinterpret_cast<float4*>(v + 4) = *reinterpret_cast<const float4*>(&Vs[n * D + tc * 8 + 4]);
#pragma unroll
                for (int i = 0; i < 4; i++)
#pragma unroll
                    for (int j = 0; j < 8; j++)
                        o_acc[i][j] += p[i] * v[j];
            }
        }
    }

#pragma unroll
    for (int i = 0; i < 4; i++) {
        int m = tr * 4 + i;
        float inv_l = 1.0f / row_l[m];
        float* orow = O + ((size_t)(b * S + q0 + m) * H + h) * D + tc * 8;
#pragma unroll
        for (int j = 0; j < 8; j += 4) {
            float4 v = make_float4(o_acc[i][j] * inv_l, o_acc[i][j + 1] * inv_l,
                                   o_acc[i][j + 2] * inv_l, o_acc[i][j + 3] * inv_l);
            *reinterpret_cast<float4*>(orow + j) = v;
        }
    }
}

// ---------------- host ----------------
extern "C" void kernel_launch(void* const* d_in, const int* in_sizes, int n_in,
                              void* d_out, int out_size)
{
    const float* x  = (const float*)d_in[0];
    const float* fc = (const float*)d_in[1];
    const float* wq = (const float*)d_in[2];
    const float* wk = (const float*)d_in[3];
    const float* wv = (const float*)d_in[4];
    const float* wo = (const float*)d_in[5];
    float* out = (float*)d_out;

    float *pq, *pk, *pv, *po;
    cudaGetSymbolAddress((void**)&pq, g_q);
    cudaGetSymbolAddress((void**)&pk, g_k);
    cudaGetSymbolAddress((void**)&pv, g_v);
    cudaGetSymbolAddress((void**)&po, g_o);
    __nv_bfloat16 *xa_hi, *xa_lo, *oa_hi, *oa_lo;
    __nv_bfloat16 *wqT_hi, *wqT_lo, *wkT_hi, *wkT_lo, *wvT_hi, *wvT_lo, *woT_hi, *woT_lo;
    cudaGetSymbolAddress((void**)&xa_hi, g_xa_hi);
    cudaGetSymbolAddress((void**)&xa_lo, g_xa_lo);
    cudaGetSymbolAddress((void**)&oa_hi, g_oa_hi);
    cudaGetSymbolAddress((void**)&oa_lo, g_oa_lo);
    cudaGetSymbolAddress((void**)&wqT_hi, g_wqT_hi);
    cudaGetSymbolAddress((void**)&wqT_lo, g_wqT_lo);
    cudaGetSymbolAddress((void**)&wkT_hi, g_wkT_hi);
    cudaGetSymbolAddress((void**)&wkT_lo, g_wkT_lo);
    cudaGetSymbolAddress((void**)&wvT_hi, g_wvT_hi);
    cudaGetSymbolAddress((void**)&wvT_lo, g_wvT_lo);
    cudaGetSymbolAddress((void**)&woT_hi, g_woT_hi);
    cudaGetSymbolAddress((void**)&woT_lo, g_woT_lo);

    cudaFuncSetAttribute(gemm_tc, cudaFuncAttributeMaxDynamicSharedMemorySize, GSM_BYTES);

    // split x into (hi, lo) bf16
    {
        int n4 = MROWS * HID / 4;
        split_f32<<<(n4 + 255) / 256, 256>>>((const float4*)x,
                                             (__nv_bfloat162*)xa_hi, (__nv_bfloat162*)xa_lo, n4);
    }
    // transpose + split weights
    {
        dim3 blk(32, 8);
        transpose_split<<<dim3(ND_Q / 32, HID / 32), blk>>>(wq, wqT_hi, wqT_lo, HID, ND_Q);
        transpose_split<<<dim3(ND_KV / 32, HID / 32), blk>>>(wk, wkT_hi, wkT_lo, HID, ND_KV);
        transpose_split<<<dim3(ND_KV / 32, HID / 32), blk>>>(wv, wvT_hi, wvT_lo, HID, ND_KV);
        transpose_split<<<dim3(ND_Q / 32, ND_Q / 32), blk>>>(wo, woT_hi, woT_lo, ND_Q, HID);
    }
    // QKV projections (tensor cores, bf16x3)
    {
        gemm_tc<<<dim3(ND_Q / GBN, MROWS / GBM), 256, GSM_BYTES>>>(
            xa_hi, xa_lo, wqT_hi, wqT_lo, pq, MROWS, ND_Q, HID);
        gemm_tc<<<dim3(ND_KV / GBN, MROWS / GBM), 256, GSM_BYTES>>>(
            xa_hi, xa_lo, wkT_hi, wkT_lo, pk, MROWS, ND_KV, HID);
        gemm_tc<<<dim3(ND_KV / GBN, MROWS / GBM), 256, GSM_BYTES>>>(
            xa_hi, xa_lo, wvT_hi, wvT_lo, pv, MROWS, ND_KV, HID);
    }
    // RoPE
    {
        int total = MROWS * H * (D / 2) + MROWS * KVH * (D / 2);
        rope_kernel<<<(total + 255) / 256, 256>>>(pq, pk, fc);
    }
    // attention
    {
        size_t smem = (size_t)(D * AB_M + D * AB_N + AB_N * D +
                               AB_M * PS_STRIDE + 3 * AB_M) * sizeof(float);
        cudaFuncSetAttribute(attn_kernel, cudaFuncAttributeMaxDynamicSharedMemorySize, (int)smem);
        dim3 grid(S / AB_M, H, B);
        attn_kernel<<<grid, 256, smem>>>(pq, pk, pv, po);
    }
    // split attention output, then output projection (tensor cores, bf16x3)
    {
        int n4 = MROWS * ND_Q / 4;
        split_f32<<<(n4 + 255) / 256, 256>>>((const float4*)po,
                                             (__nv_bfloat162*)oa_hi, (__nv_bfloat162*)oa_lo, n4);
        gemm_tc<<<dim3(HID / GBN, MROWS / GBM), 256, GSM_BYTES>>>(
            oa_hi, oa_lo, woT_hi, woT_lo, out, MROWS, HID, ND_Q);
    }
}

// round 6
// speedup vs baseline: 2.7634x; 1.7263x over previous
#include <cuda_runtime.h>
#include <cuda_bf16.h>
#include <cstdint>

#define B 2
#define S 2048
#define HID 2048
#define H 16
#define KVH 4
#define D 128
#define GROUPS (H / KVH)
#define MROWS (B * S)          // 4096
#define ND_Q (H * D)           // 2048
#define ND_KV (KVH * D)        // 512
#define QK_SCALE 0.08838834764831845f

// ---------------- scratch (no allocations allowed) ----------------
__device__ float g_q[MROWS * H * D];
__device__ float g_k[MROWS * KVH * D];
__device__ float g_v[MROWS * KVH * D];

__device__ __align__(16) __nv_bfloat16 g_xa_hi[MROWS * HID];
__device__ __align__(16) __nv_bfloat16 g_xa_lo[MROWS * HID];
__device__ __align__(16) __nv_bfloat16 g_oa_hi[MROWS * ND_Q];
__device__ __align__(16) __nv_bfloat16 g_oa_lo[MROWS * ND_Q];
__device__ __align__(16) __nv_bfloat16 g_wqT_hi[ND_Q * HID];
__device__ __align__(16) __nv_bfloat16 g_wqT_lo[ND_Q * HID];
__device__ __align__(16) __nv_bfloat16 g_wkT_hi[ND_KV * HID];
__device__ __align__(16) __nv_bfloat16 g_wkT_lo[ND_KV * HID];
__device__ __align__(16) __nv_bfloat16 g_wvT_hi[ND_KV * HID];
__device__ __align__(16) __nv_bfloat16 g_wvT_lo[ND_KV * HID];
__device__ __align__(16) __nv_bfloat16 g_woT_hi[HID * ND_Q];
__device__ __align__(16) __nv_bfloat16 g_woT_lo[HID * ND_Q];
// attention operand layouts
__device__ __align__(16) __nv_bfloat16 g_qs_hi[B * H * S * D];    // [b][h][s][d]
__device__ __align__(16) __nv_bfloat16 g_qs_lo[B * H * S * D];
__device__ __align__(16) __nv_bfloat16 g_ks_hi[B * KVH * S * D];  // [b][kvh][s][d]
__device__ __align__(16) __nv_bfloat16 g_ks_lo[B * KVH * S * D];
__device__ __align__(16) __nv_bfloat16 g_vt_hi[B * KVH * D * S];  // [b][kvh][d][s]
__device__ __align__(16) __nv_bfloat16 g_vt_lo[B * KVH * D * S];

// ---------------- helpers ----------------
__device__ __forceinline__ uint32_t smem_u32(const void* p) {
    uint32_t a;
    asm("{ .reg .u64 t; cvta.to.shared.u64 t, %1; cvt.u32.u64 %0, t; }" : "=r"(a) : "l"(p));
    return a;
}
__device__ __forceinline__ void cp_async16(uint32_t saddr, const void* gaddr) {
    asm volatile("cp.async.cg.shared.global [%0], [%1], 16;" :: "r"(saddr), "l"(gaddr)
                 : "memory");
}
__device__ __forceinline__ void cp_commit() {
    asm volatile("cp.async.commit_group;" ::: "memory");
}
template <int N>
__device__ __forceinline__ void cp_wait() {
    asm volatile("cp.async.wait_group %0;" :: "n"(N) : "memory");
}
__device__ __forceinline__ void ldsm_x4(uint32_t* r, uint32_t addr) {
    asm volatile("ldmatrix.sync.aligned.m8n8.x4.shared.b16 {%0,%1,%2,%3}, [%4];"
                 : "=r"(r[0]), "=r"(r[1]), "=r"(r[2]), "=r"(r[3]) : "r"(addr));
}
__device__ __forceinline__ void mma_bf16(float* c, const uint32_t* a, const uint32_t* b) {
    asm volatile(
        "mma.sync.aligned.m16n8k16.row.col.f32.bf16.bf16.f32 "
        "{%0,%1,%2,%3}, {%4,%5,%6,%7}, {%8,%9}, {%0,%1,%2,%3};"
        : "+f"(c[0]), "+f"(c[1]), "+f"(c[2]), "+f"(c[3])
        : "r"(a[0]), "r"(a[1]), "r"(a[2]), "r"(a[3]), "r"(b[0]), "r"(b[1]));
}
__device__ __forceinline__ void split2(float x, float y, uint32_t& hi, uint32_t& lo) {
    __nv_bfloat16 hx = __float2bfloat16(x), hy = __float2bfloat16(y);
    __nv_bfloat162 hh; hh.x = hx; hh.y = hy;
    __nv_bfloat162 ll;
    ll.x = __float2bfloat16(x - __bfloat162float(hx));
    ll.y = __float2bfloat16(y - __bfloat162float(hy));
    hi = *reinterpret_cast<uint32_t*>(&hh);
    lo = *reinterpret_cast<uint32_t*>(&ll);
}

// ---------------- split fp32 -> (hi, lo) bf16 ----------------
__global__ void split_f32(const float4* __restrict__ src, __nv_bfloat162* __restrict__ hi,
                          __nv_bfloat162* __restrict__ lo, int n4) {
    int i = blockIdx.x * blockDim.x + threadIdx.x;
    if (i >= n4) return;
    float4 v = src[i];
    __nv_bfloat16 h0 = __float2bfloat16(v.x);
    __nv_bfloat16 h1 = __float2bfloat16(v.y);
    __nv_bfloat16 h2 = __float2bfloat16(v.z);
    __nv_bfloat16 h3 = __float2bfloat16(v.w);
    hi[2 * i]     = __halves2bfloat162(h0, h1);
    hi[2 * i + 1] = __halves2bfloat162(h2, h3);
    lo[2 * i]     = __halves2bfloat162(__float2bfloat16(v.x - __bfloat162float(h0)),
                                       __float2bfloat16(v.y - __bfloat162float(h1)));
    lo[2 * i + 1] = __halves2bfloat162(__float2bfloat16(v.z - __bfloat162float(h2)),
                                       __float2bfloat16(v.w - __bfloat162float(h3)));
}

// ---------------- transpose + split: W[K,N] fp32 -> T[N,K] (hi, lo) bf16 ----------------
__global__ void transpose_split(const float* __restrict__ W, __nv_bfloat16* __restrict__ Thi,
                                __nv_bfloat16* __restrict__ Tlo, int K, int N) {
    __shared__ float t[32][33];
    int k0 = blockIdx.y * 32, n0 = blockIdx.x * 32;
    int tx = threadIdx.x, ty = threadIdx.y;
#pragma unroll
    for (int j = 0; j < 4; j++)
        t[ty + j * 8][tx] = W[(size_t)(k0 + ty + j * 8) * N + n0 + tx];
    __syncthreads();
#pragma unroll
    for (int j = 0; j < 4; j++) {
        int n = n0 + ty + j * 8;
        float v = t[tx][ty + j * 8];
        __nv_bfloat16 h = __float2bfloat16(v);
        Thi[(size_t)n * K + k0 + tx] = h;
        Tlo[(size_t)n * K + k0 + tx] = __float2bfloat16(v - __bfloat162float(h));
    }
}

// ---------------- bf16x3 tensor-core GEMM via mma.sync ----------------
#define GBM 128
#define GBN 128
#define GBK 32
#define LDT 40
#define TILE_E (GBM * LDT)
#define STAGE_E (4 * TILE_E)
#define GSM_BYTES (2 * STAGE_E * 2)

__global__ __launch_bounds__(256, 1)
void gemm_tc(const __nv_bfloat16* __restrict__ Ahi, const __nv_bfloat16* __restrict__ Alo,
             const __nv_bfloat16* __restrict__ Bhi, const __nv_bfloat16* __restrict__ Blo,
             float* __restrict__ C, int M, int N, int K)
{
    extern __shared__ __nv_bfloat16 sm[];
    const uint32_t sb = smem_u32(sm);
    const int tid = threadIdx.x;
    const int wid = tid / 32, lane = tid % 32;
    const int warp_m = wid % 4;
    const int warp_n = wid / 4;
    const int m0 = blockIdx.y * GBM, n0 = blockIdx.x * GBN;

    const int ld_row = tid / 4;
    const int ld_col = (tid % 4) * 8;

    const __nv_bfloat16* pAh = Ahi + (size_t)(m0 + ld_row) * K + ld_col;
    const __nv_bfloat16* pAl = Alo + (size_t)(m0 + ld_row) * K + ld_col;
    const __nv_bfloat16* pBh = Bhi + (size_t)(n0 + ld_row) * K + ld_col;
    const __nv_bfloat16* pBl = Blo + (size_t)(n0 + ld_row) * K + ld_col;
    const size_t rstep64 = (size_t)64 * K;

    auto load_chunk = [&](int t, int stg) {
        uint32_t sbase = sb + (uint32_t)(stg * STAGE_E) * 2u;
        uint32_t soff = ((uint32_t)ld_row * LDT + (uint32_t)ld_col) * 2u;
        const int kk = t * GBK;
#pragma unroll
        for (int j = 0; j < 2; j++) {
            uint32_t so = soff + (uint32_t)(j * 64 * LDT) * 2u;
            cp_async16(sbase + 0 * TILE_E * 2 + so, pAh + kk + j * rstep64);
            cp_async16(sbase + 1 * TILE_E * 2 + so, pAl + kk + j * rstep64);
            cp_async16(sbase + 2 * TILE_E * 2 + so, pBh + kk + j * rstep64);
            cp_async16(sbase + 3 * TILE_E * 2 + so, pBl + kk + j * rstep64);
        }
    };

    float acc[2][8][4];
#pragma unroll
    for (int i = 0; i < 2; i++)
#pragma unroll
        for (int j = 0; j < 8; j++)
#pragma unroll
            for (int r = 0; r < 4; r++) acc[i][j][r] = 0.f;

    const int nch = K / GBK;
    load_chunk(0, 0);
    cp_commit();

    for (int t = 0; t < nch; t++) {
        const int stg = t & 1;
        if (t + 1 < nch) {
            load_chunk(t + 1, stg ^ 1);
            cp_commit();
            cp_wait<1>();
        } else {
            cp_wait<0>();
        }
        __syncthreads();

        const uint32_t sbase = sb + (uint32_t)(stg * STAGE_E) * 2u;
#pragma unroll
        for (int ks = 0; ks < 2; ks++) {
            const uint32_t kc = (uint32_t)(ks * 16 + (lane / 16) * 8);
            uint32_t ah[2][4], al[2][4];
#pragma unroll
            for (int mt = 0; mt < 2; mt++) {
                uint32_t row = (uint32_t)(warp_m * 32 + mt * 16 + (lane % 16));
                uint32_t off = (row * LDT + kc) * 2u;
                ldsm_x4(ah[mt], sbase + 0 * TILE_E * 2 + off);
                ldsm_x4(al[mt], sbase + 1 * TILE_E * 2 + off);
            }
            uint32_t bh[8][2], bl[8][2];
#pragma unroll
            for (int ng = 0; ng < 4; ng++) {
                uint32_t row = (uint32_t)(warp_n * 64 + ng * 16 + (lane % 8) +
                                          ((lane / 8) % 2) * 8);
                uint32_t off = (row * LDT + kc) * 2u;
                uint32_t r[4];
                ldsm_x4(r, sbase + 2 * TILE_E * 2 + off);
                bh[2 * ng][0] = r[0]; bh[2 * ng][1] = r[2];
                bh[2 * ng + 1][0] = r[1]; bh[2 * ng + 1][1] = r[3];
                ldsm_x4(r, sbase + 3 * TILE_E * 2 + off);
                bl[2 * ng][0] = r[0]; bl[2 * ng][1] = r[2];
                bl[2 * ng + 1][0] = r[1]; bl[2 * ng + 1][1] = r[3];
            }
#pragma unroll
            for (int mt = 0; mt < 2; mt++)
#pragma unroll
                for (int nt = 0; nt < 8; nt++) {
                    mma_bf16(acc[mt][nt], ah[mt], bh[nt]);
                    mma_bf16(acc[mt][nt], ah[mt], bl[nt]);
                    mma_bf16(acc[mt][nt], al[mt], bh[nt]);
                }
        }
        __syncthreads();
    }

#pragma unroll
    for (int mt = 0; mt < 2; mt++) {
        int row = m0 + warp_m * 32 + mt * 16 + lane / 4;
#pragma unroll
        for (int nt = 0; nt < 8; nt++) {
            int col = n0 + warp_n * 64 + nt * 8 + (lane % 4) * 2;
            float2 v0 = make_float2(acc[mt][nt][0], acc[mt][nt][1]);
            float2 v1 = make_float2(acc[mt][nt][2], acc[mt][nt][3]);
            *reinterpret_cast<float2*>(&C[(size_t)row * N + col]) = v0;
            *reinterpret_cast<float2*>(&C[(size_t)(row + 8) * N + col]) = v1;
        }
    }
}

// ---------------- RoPE + scale + split, Q: [b,s,h,d] f32 -> [b,h,s,d] hi/lo ----------------
__global__ void rope_split_q(const float* __restrict__ q, const float* __restrict__ fc,
                             __nv_bfloat16* __restrict__ qh, __nv_bfloat16* __restrict__ ql) {
    int idx = blockIdx.x * blockDim.x + threadIdx.x;
    if (idx >= B * H * S * (D / 2)) return;
    int i = idx % (D / 2);
    int s = (idx / (D / 2)) % S;
    int h = (idx / (D / 2) / S) % H;
    int b = idx / (D / 2) / S / H;
    float c  = fc[(s * (D / 2) + i) * 2 + 0];
    float sn = fc[(s * (D / 2) + i) * 2 + 1];
    const float* p = q + ((size_t)(b * S + s) * H + h) * D + 2 * i;
    float x0 = p[0], x1 = p[1];
    float r0 = (x0 * c - x1 * sn) * QK_SCALE;
    float r1 = (x0 * sn + x1 * c) * QK_SCALE;
    __nv_bfloat16 h0 = __float2bfloat16(r0), h1 = __float2bfloat16(r1);
    size_t o = ((size_t)(b * H + h) * S + s) * D + 2 * i;
    *reinterpret_cast<__nv_bfloat162*>(qh + o) = __halves2bfloat162(h0, h1);
    *reinterpret_cast<__nv_bfloat162*>(ql + o) =
        __halves2bfloat162(__float2bfloat16(r0 - __bfloat162float(h0)),
                           __float2bfloat16(r1 - __bfloat162float(h1)));
}

// ---------------- RoPE + split, K: [b,s,kvh,d] f32 -> [b,kvh,s,d] hi/lo ----------------
__global__ void rope_split_k(const float* __restrict__ k, const float* __restrict__ fc,
                             __nv_bfloat16* __restrict__ kh, __nv_bfloat16* __restrict__ kl) {
    int idx = blockIdx.x * blockDim.x + threadIdx.x;
    if (idx >= B * KVH * S * (D / 2)) return;
    int i = idx % (D / 2);
    int s = (idx / (D / 2)) % S;
    int h = (idx / (D / 2) / S) % KVH;
    int b = idx / (D / 2) / S / KVH;
    float c  = fc[(s * (D / 2) + i) * 2 + 0];
    float sn = fc[(s * (D / 2) + i) * 2 + 1];
    const float* p = k + ((size_t)(b * S + s) * KVH + h) * D + 2 * i;
    float x0 = p[0], x1 = p[1];
    float r0 = x0 * c - x1 * sn;
    float r1 = x0 * sn + x1 * c;
    __nv_bfloat16 h0 = __float2bfloat16(r0), h1 = __float2bfloat16(r1);
    size_t o = ((size_t)(b * KVH + h) * S + s) * D + 2 * i;
    *reinterpret_cast<__nv_bfloat162*>(kh + o) = __halves2bfloat162(h0, h1);
    *reinterpret_cast<__nv_bfloat162*>(kl + o) =
        __halves2bfloat162(__float2bfloat16(r0 - __bfloat162float(h0)),
                           __float2bfloat16(r1 - __bfloat162float(h1)));
}

// ---------------- V transpose + split: [b,s,kvh,d] f32 -> [b,kvh,d,s] hi/lo ----------------
__global__ void v_split_t(const float* __restrict__ v, __nv_bfloat16* __restrict__ vh,
                          __nv_bfloat16* __restrict__ vl) {
    __shared__ float t[32][33];
    int d0 = blockIdx.x * 32, s0 = blockIdx.y * 32;
    int bk = blockIdx.z;
    int b = bk / KVH, kvh = bk % KVH;
    int tx = threadIdx.x, ty = threadIdx.y;
#pragma unroll
    for (int j = 0; j < 4; j++)
        t[ty + j * 8][tx] = v[((size_t)(b * S + s0 + ty + j * 8) * KVH + kvh) * D + d0 + tx];
    __syncthreads();
#pragma unroll
    for (int j = 0; j < 4; j++) {
        int d = d0 + ty + j * 8;
        float val = t[tx][ty + j * 8];
        __nv_bfloat16 h = __float2bfloat16(val);
        size_t o = ((size_t)(b * KVH + kvh) * D + d) * S + s0 + tx;
        vh[o] = h;
        vl[o] = __float2bfloat16(val - __bfloat162float(h));
    }
}

// ---------------- tensor-core flash attention (bf16x3), causal, GQA ----------------
#define AM 128
#define AN 64
#define LQ 136   // Q/K smem row stride (bf16 elems)
#define LV 72    // V^T smem row stride
#define SQH 0
#define SQL 17408
#define SST 34816          // start of KV stages
#define STSZ 35840         // one stage (elems): KH 8704, KL 8704, VH 9216, VL 9216
#define OKL 8704
#define OVH 17408
#define OVL 26624
#define ATT_SMEM ((SST + 2 * STSZ) * 2)   // 212992 bytes

__global__ __launch_bounds__(256, 1)
void attn_tc(const __nv_bfloat16* __restrict__ Qh, const __nv_bfloat16* __restrict__ Ql,
             const __nv_bfloat16* __restrict__ Kh, const __nv_bfloat16* __restrict__ Kl,
             const __nv_bfloat16* __restrict__ Vh, const __nv_bfloat16* __restrict__ Vl,
             __nv_bfloat16* __restrict__ Ohi, __nv_bfloat16* __restrict__ Olo)
{
    extern __shared__ __nv_bfloat16 sma[];
    const uint32_t sb = smem_u32(sma);
    const int tid = threadIdx.x, wid = tid / 32, lane = tid % 32;
    const int bx = blockIdx.x, h = blockIdx.y, b = blockIdx.z;
    const int kvh = h / GROUPS;
    const int q0 = bx * AM;

    const __nv_bfloat16* qhp = Qh + ((size_t)(b * H + h) * S + q0) * D;
    const __nv_bfloat16* qlp = Ql + ((size_t)(b * H + h) * S + q0) * D;
    const __nv_bfloat16* khp = Kh + (size_t)(b * KVH + kvh) * S * D;
    const __nv_bfloat16* klp = Kl + (size_t)(b * KVH + kvh) * S * D;
    const __nv_bfloat16* vhp = Vh + (size_t)(b * KVH + kvh) * D * S;
    const __nv_bfloat16* vlp = Vl + (size_t)(b * KVH + kvh) * D * S;

    // load Q tile (hi+lo) via cp.async: 128 rows x 128 cols
#pragma unroll
    for (int j = 0; j < 8; j++) {
        int seg = tid + j * 256;            // 0..2047
        int row = seg >> 4, c = (seg & 15) * 8;
        cp_async16(sb + (uint32_t)(SQH + row * LQ + c) * 2, qhp + (size_t)row * D + c);
        cp_async16(sb + (uint32_t)(SQL + row * LQ + c) * 2, qlp + (size_t)row * D + c);
    }
    cp_commit();

    auto load_kv = [&](int t, int stg) {
        uint32_t sbase = sb + (uint32_t)(SST + stg * STSZ) * 2;
        int kv0 = t * AN;
#pragma unroll
        for (int j = 0; j < 4; j++) {
            int seg = tid + j * 256;        // 0..1023
            int row = seg >> 4, c = (seg & 15) * 8;
            cp_async16(sbase + (uint32_t)(row * LQ + c) * 2,
                       khp + (size_t)(kv0 + row) * D + c);
            cp_async16(sbase + (uint32_t)(OKL + row * LQ + c) * 2,
                       klp + (size_t)(kv0 + row) * D + c);
        }
#pragma unroll
        for (int j = 0; j < 4; j++) {
            int seg = tid + j * 256;
            int row = seg >> 3, c = (seg & 7) * 8;
            cp_async16(sbase + (uint32_t)(OVH + row * LV + c) * 2,
                       vhp + (size_t)row * S + kv0 + c);
            cp_async16(sbase + (uint32_t)(OVL + row * LV + c) * 2,
                       vlp + (size_t)row * S + kv0 + c);
        }
    };

    float m0 = -1e30f, m1 = -1e30f, l0 = 0.f, l1 = 0.f;
    float oacc[16][4];
#pragma unroll
    for (int i = 0; i < 16; i++)
#pragma unroll
        for (int j = 0; j < 4; j++) oacc[i][j] = 0.f;

    const int ntiles = 2 * (bx + 1);
    load_kv(0, 0);
    cp_commit();

    for (int t = 0; t < ntiles; t++) {
        if (t + 1 < ntiles) {
            load_kv(t + 1, (t + 1) & 1);
            cp_commit();
            cp_wait<1>();
        } else {
            cp_wait<0>();
        }
        __syncthreads();
        const uint32_t stg = sb + (uint32_t)(SST + (t & 1) * STSZ) * 2;

        // ---- S = Q K^T (bf16x3) ----
        float sacc[8][4];
#pragma unroll
        for (int i = 0; i < 8; i++)
#pragma unroll
            for (int j = 0; j < 4; j++) sacc[i][j] = 0.f;

#pragma unroll
        for (int ks = 0; ks < 8; ks++) {
            const uint32_t kc = (uint32_t)(ks * 16 + (lane >> 4) * 8);
            uint32_t ah[4], al[4];
            const uint32_t qrow = (uint32_t)(wid * 16 + (lane & 15));
            ldsm_x4(ah, sb + (SQH + qrow * LQ + kc) * 2);
            ldsm_x4(al, sb + (SQL + qrow * LQ + kc) * 2);
            const uint32_t brow = (uint32_t)((lane & 7) + ((lane >> 3) & 1) * 8);
#pragma unroll
            for (int ng = 0; ng < 4; ng++) {
                uint32_t row = (uint32_t)(ng * 16) + brow;
                uint32_t rh[4], rl[4];
                ldsm_x4(rh, stg + (row * LQ + kc) * 2);
                ldsm_x4(rl, stg + (OKL + row * LQ + kc) * 2);
                uint32_t b0[2] = {rh[0], rh[2]}, b1[2] = {rh[1], rh[3]};
                uint32_t bl0[2] = {rl[0], rl[2]}, bl1[2] = {rl[1], rl[3]};
                mma_bf16(sacc[2 * ng],     ah, b0);
                mma_bf16(sacc[2 * ng],     ah, bl0);
                mma_bf16(sacc[2 * ng],     al, b0);
                mma_bf16(sacc[2 * ng + 1], ah, b1);
                mma_bf16(sacc[2 * ng + 1], ah, bl1);
                mma_bf16(sacc[2 * ng + 1], al, b1);
            }
        }

        // ---- causal mask (only diagonal tiles) ----
        const int row0 = q0 + wid * 16 + (lane >> 2);
        if (t >= 2 * bx) {
            const int kvb = t * AN + 2 * (lane & 3);
#pragma unroll
            for (int nt = 0; nt < 8; nt++) {
                int col = kvb + nt * 8;
                if (col     > row0)     sacc[nt][0] = -1e30f;
                if (col + 1 > row0)     sacc[nt][1] = -1e30f;
                if (col     > row0 + 8) sacc[nt][2] = -1e30f;
                if (col + 1 > row0 + 8) sacc[nt][3] = -1e30f;
            }
        }

        // ---- online softmax ----
        float mx0 = -1e30f, mx1 = -1e30f;
#pragma unroll
        for (int nt = 0; nt < 8; nt++) {
            mx0 = fmaxf(mx0, fmaxf(sacc[nt][0], sacc[nt][1]));
            mx1 = fmaxf(mx1, fmaxf(sacc[nt][2], sacc[nt][3]));
        }
        mx0 = fmaxf(mx0, __shfl_xor_sync(0xffffffffu, mx0, 1));
        mx0 = fmaxf(mx0, __shfl_xor_sync(0xffffffffu, mx0, 2));
        mx1 = fmaxf(mx1, __shfl_xor_sync(0xffffffffu, mx1, 1));
        mx1 = fmaxf(mx1, __shfl_xor_sync(0xffffffffu, mx1, 2));
        float nm0 = fmaxf(m0, mx0), nm1 = fmaxf(m1, mx1);
        float f0 = __expf(m0 - nm0), f1 = __expf(m1 - nm1);
        float sum0 = 0.f, sum1 = 0.f;
#pragma unroll
        for (int nt = 0; nt < 8; nt++) {
            sacc[nt][0] = __expf(sacc[nt][0] - nm0);
            sacc[nt][1] = __expf(sacc[nt][1] - nm0);
            sacc[nt][2] = __expf(sacc[nt][2] - nm1);
            sacc[nt][3] = __expf(sacc[nt][3] - nm1);
            sum0 += sacc[nt][0] + sacc[nt][1];
            sum1 += sacc[nt][2] + sacc[nt][3];
        }
        sum0 += __shfl_xor_sync(0xffffffffu, sum0, 1);
        sum0 += __shfl_xor_sync(0xffffffffu, sum0, 2);
        sum1 += __shfl_xor_sync(0xffffffffu, sum1, 1);
        sum1 += __shfl_xor_sync(0xffffffffu, sum1, 2);
        l0 = l0 * f0 + sum0;
        l1 = l1 * f1 + sum1;
        m0 = nm0;
        m1 = nm1;
#pragma unroll
        for (int nt = 0; nt < 16; nt++) {
            oacc[nt][0] *= f0;
            oacc[nt][1] *= f0;
            oacc[nt][2] *= f1;
            oacc[nt][3] *= f1;
        }

        // ---- O += P V (bf16x3, P from accumulator layout) ----
#pragma unroll
        for (int ks2 = 0; ks2 < 4; ks2++) {
            const float* ce = sacc[2 * ks2];
            const float* co = sacc[2 * ks2 + 1];
            uint32_t ph[4], pl[4];
            split2(ce[0], ce[1], ph[0], pl[0]);
            split2(ce[2], ce[3], ph[1], pl[1]);
            split2(co[0], co[1], ph[2], pl[2]);
            split2(co[2], co[3], ph[3], pl[3]);
            const uint32_t kc2 = (uint32_t)(ks2 * 16 + (lane >> 4) * 8);
            const uint32_t brow = (uint32_t)((lane & 7) + ((lane >> 3) & 1) * 8);
#pragma unroll
            for (int ng = 0; ng < 8; ng++) {
                uint32_t row = (uint32_t)(ng * 16) + brow;
                uint32_t rh[4], rl[4];
                ldsm_x4(rh, stg + (OVH + row * LV + kc2) * 2);
                ldsm_x4(rl, stg + (OVL + row * LV + kc2) * 2);
                uint32_t b0[2] = {rh[0], rh[2]}, b1[2] = {rh[1], rh[3]};
                uint32_t bl0[2] = {rl[0], rl[2]}, bl1[2] = {rl[1], rl[3]};
                mma_bf16(oacc[2 * ng],     ph, b0);
                mma_bf16(oacc[2 * ng],     pl, b0);
                mma_bf16(oacc[2 * ng],     ph, bl0);
                mma_bf16(oacc[2 * ng + 1], ph, b1);
                mma_bf16(oacc[2 * ng + 1], pl, b1);
                mma_bf16(oacc[2 * ng + 1], ph, bl1);
            }
        }
        __syncthreads();
    }

    // ---- epilogue: normalize, split hi/lo, store [b,s,h,d] ----
    const float inv0 = 1.f / l0, inv1 = 1.f / l1;
    const int row0 = q0 + wid * 16 + (lane >> 2);
#pragma unroll
    for (int nt = 0; nt < 16; nt++) {
        int col = nt * 8 + 2 * (lane & 3);
        size_t o0 = ((size_t)(b * S + row0) * H + h) * D + col;
        size_t o1 = ((size_t)(b * S + row0 + 8) * H + h) * D + col;
        float v0 = oacc[nt][0] * inv0, v1 = oacc[nt][1] * inv0;
        float v2 = oacc[nt][2] * inv1, v3 = oacc[nt][3] * inv1;
        uint32_t hh, ll;
        split2(v0, v1, hh, ll);
        *reinterpret_cast<uint32_t*>(Ohi + o0) = hh;
        *reinterpret_cast<uint32_t*>(Olo + o0) = ll;
        split2(v2, v3, hh, ll);
        *reinterpret_cast<uint32_t*>(Ohi + o1) = hh;
        *reinterpret_cast<uint32_t*>(Olo + o1) = ll;
    }
}

// ---------------- host ----------------
extern "C" void kernel_launch(void* const* d_in, const int* in_sizes, int n_in,
                              void* d_out, int out_size)
{
    const float* x  = (const float*)d_in[0];
    const float* fc = (const float*)d_in[1];
    const float* wq = (const float*)d_in[2];
    const float* wk = (const float*)d_in[3];
    const float* wv = (const float*)d_in[4];
    const float* wo = (const float*)d_in[5];
    float* out = (float*)d_out;

    float *pq, *pk, *pv;
    cudaGetSymbolAddress((void**)&pq, g_q);
    cudaGetSymbolAddress((void**)&pk, g_k);
    cudaGetSymbolAddress((void**)&pv, g_v);
    __nv_bfloat16 *xa_hi, *xa_lo, *oa_hi, *oa_lo;
    __nv_bfloat16 *wqT_hi, *wqT_lo, *wkT_hi, *wkT_lo, *wvT_hi, *wvT_lo, *woT_hi, *woT_lo;
    __nv_bfloat16 *qs_hi, *qs_lo, *ks_hi, *ks_lo, *vt_hi, *vt_lo;
    cudaGetSymbolAddress((void**)&xa_hi, g_xa_hi);
    cudaGetSymbolAddress((void**)&xa_lo, g_xa_lo);
    cudaGetSymbolAddress((void**)&oa_hi, g_oa_hi);
    cudaGetSymbolAddress((void**)&oa_lo, g_oa_lo);
    cudaGetSymbolAddress((void**)&wqT_hi, g_wqT_hi);
    cudaGetSymbolAddress((void**)&wqT_lo, g_wqT_lo);
    cudaGetSymbolAddress((void**)&wkT_hi, g_wkT_hi);
    cudaGetSymbolAddress((void**)&wkT_lo, g_wkT_lo);
    cudaGetSymbolAddress((void**)&wvT_hi, g_wvT_hi);
    cudaGetSymbolAddress((void**)&wvT_lo, g_wvT_lo);
    cudaGetSymbolAddress((void**)&woT_hi, g_woT_hi);
    cudaGetSymbolAddress((void**)&woT_lo, g_woT_lo);
    cudaGetSymbolAddress((void**)&qs_hi, g_qs_hi);
    cudaGetSymbolAddress((void**)&qs_lo, g_qs_lo);
    cudaGetSymbolAddress((void**)&ks_hi, g_ks_hi);
    cudaGetSymbolAddress((void**)&ks_lo, g_ks_lo);
    cudaGetSymbolAddress((void**)&vt_hi, g_vt_hi);
    cudaGetSymbolAddress((void**)&vt_lo, g_vt_lo);

    cudaFuncSetAttribute(gemm_tc, cudaFuncAttributeMaxDynamicSharedMemorySize, GSM_BYTES);
    cudaFuncSetAttribute(attn_tc, cudaFuncAttributeMaxDynamicSharedMemorySize, ATT_SMEM);

    // split x into (hi, lo) bf16
    {
        int n4 = MROWS * HID / 4;
        split_f32<<<(n4 + 255) / 256, 256>>>((const float4*)x,
                                             (__nv_bfloat162*)xa_hi, (__nv_bfloat162*)xa_lo, n4);
    }
    // transpose + split weights
    {
        dim3 blk(32, 8);
        transpose_split<<<dim3(ND_Q / 32, HID / 32), blk>>>(wq, wqT_hi, wqT_lo, HID, ND_Q);
        transpose_split<<<dim3(ND_KV / 32, HID / 32), blk>>>(wk, wkT_hi, wkT_lo, HID, ND_KV);
        transpose_split<<<dim3(ND_KV / 32, HID / 32), blk>>>(wv, wvT_hi, wvT_lo, HID, ND_KV);
        transpose_split<<<dim3(ND_Q / 32, ND_Q / 32), blk>>>(wo, woT_hi, woT_lo, ND_Q, HID);
    }
    // QKV projections (tensor cores, bf16x3)
    {
        gemm_tc<<<dim3(ND_Q / GBN, MROWS / GBM), 256, GSM_BYTES>>>(
            xa_hi, xa_lo, wqT_hi, wqT_lo, pq, MROWS, ND_Q, HID);
        gemm_tc<<<dim3(ND_KV / GBN, MROWS / GBM), 256, GSM_BYTES>>>(
            xa_hi, xa_lo, wkT_hi, wkT_lo, pk, MROWS, ND_KV, HID);
        gemm_tc<<<dim3(ND_KV / GBN, MROWS / GBM), 256, GSM_BYTES>>>(
            xa_hi, xa_lo, wvT_hi, wvT_lo, pv, MROWS, ND_KV, HID);
    }
    // RoPE + split + relayout for attention
    {
        int nq = B * H * S * (D / 2);
        rope_split_q<<<(nq + 255) / 256, 256>>>(pq, fc, qs_hi, qs_lo);
        int nk = B * KVH * S * (D / 2);
        rope_split_k<<<(nk + 255) / 256, 256>>>(pk, fc, ks_hi, ks_lo);
        dim3 blk(32, 8);
        v_split_t<<<dim3(D / 32, S / 32, B * KVH), blk>>>(pv, vt_hi, vt_lo);
    }
    // tensor-core flash attention (writes hi/lo O directly)
    {
        dim3 grid(S / AM, H, B);
        attn_tc<<<grid, 256, ATT_SMEM>>>(qs_hi, qs_lo, ks_hi, ks_lo, vt_hi, vt_lo,
                                         oa_hi, oa_lo);
    }
    // output projection (tensor cores, bf16x3)
    {
        gemm_tc<<<dim3(HID / GBN, MROWS / GBM), 256, GSM_BYTES>>>(
            oa_hi, oa_lo, woT_hi, woT_lo, out, MROWS, HID, ND_Q);
    }
}

// round 7
// speedup vs baseline: 3.7270x; 1.3487x over previous
#include <cuda_runtime.h>
#include <cuda_bf16.h>
#include <cuda_fp16.h>
#include <cstdint>

#define B 2
#define S 2048
#define HID 2048
#define H 16
#define KVH 4
#define D 128
#define GROUPS (H / KVH)
#define MROWS (B * S)          // 4096
#define ND_Q (H * D)           // 2048
#define ND_KV (KVH * D)        // 512
#define QK_SCALE 0.08838834764831845f

// ---------------- scratch (no allocations allowed) ----------------
__device__ float g_q[MROWS * H * D];
__device__ float g_k[MROWS * KVH * D];
__device__ float g_v[MROWS * KVH * D];

__device__ __align__(16) __half g_xa_h[MROWS * HID];      // x as fp16
__device__ __align__(16) __half g_oa_h[MROWS * ND_Q];     // attention out as fp16
__device__ __align__(16) __half g_wqT_h[ND_Q * HID];
__device__ __align__(16) __half g_wqT_l[ND_Q * HID];
__device__ __align__(16) __half g_wkT_h[ND_KV * HID];
__device__ __align__(16) __half g_wkT_l[ND_KV * HID];
__device__ __align__(16) __half g_wvT_h[ND_KV * HID];
__device__ __align__(16) __half g_wvT_l[ND_KV * HID];
__device__ __align__(16) __half g_woT_h[HID * ND_Q];
__device__ __align__(16) __half g_woT_l[HID * ND_Q];
// attention operand layouts (bf16x3 path, unchanged)
__device__ __align__(16) __nv_bfloat16 g_qs_hi[B * H * S * D];    // [b][h][s][d]
__device__ __align__(16) __nv_bfloat16 g_qs_lo[B * H * S * D];
__device__ __align__(16) __nv_bfloat16 g_ks_hi[B * KVH * S * D];  // [b][kvh][s][d]
__device__ __align__(16) __nv_bfloat16 g_ks_lo[B * KVH * S * D];
__device__ __align__(16) __nv_bfloat16 g_vt_hi[B * KVH * D * S];  // [b][kvh][d][s]
__device__ __align__(16) __nv_bfloat16 g_vt_lo[B * KVH * D * S];

// ---------------- helpers ----------------
__device__ __forceinline__ uint32_t smem_u32(const void* p) {
    uint32_t a;
    asm("{ .reg .u64 t; cvta.to.shared.u64 t, %1; cvt.u32.u64 %0, t; }" : "=r"(a) : "l"(p));
    return a;
}
__device__ __forceinline__ void cp_async16(uint32_t saddr, const void* gaddr) {
    asm volatile("cp.async.cg.shared.global [%0], [%1], 16;" :: "r"(saddr), "l"(gaddr)
                 : "memory");
}
__device__ __forceinline__ void cp_commit() {
    asm volatile("cp.async.commit_group;" ::: "memory");
}
template <int N>
__device__ __forceinline__ void cp_wait() {
    asm volatile("cp.async.wait_group %0;" :: "n"(N) : "memory");
}
__device__ __forceinline__ void ldsm_x4(uint32_t* r, uint32_t addr) {
    asm volatile("ldmatrix.sync.aligned.m8n8.x4.shared.b16 {%0,%1,%2,%3}, [%4];"
                 : "=r"(r[0]), "=r"(r[1]), "=r"(r[2]), "=r"(r[3]) : "r"(addr));
}
__device__ __forceinline__ void mma_bf16(float* c, const uint32_t* a, const uint32_t* b) {
    asm volatile(
        "mma.sync.aligned.m16n8k16.row.col.f32.bf16.bf16.f32 "
        "{%0,%1,%2,%3}, {%4,%5,%6,%7}, {%8,%9}, {%0,%1,%2,%3};"
        : "+f"(c[0]), "+f"(c[1]), "+f"(c[2]), "+f"(c[3])
        : "r"(a[0]), "r"(a[1]), "r"(a[2]), "r"(a[3]), "r"(b[0]), "r"(b[1]));
}
__device__ __forceinline__ void mma_f16(float* c, const uint32_t* a, const uint32_t* b) {
    asm volatile(
        "mma.sync.aligned.m16n8k16.row.col.f32.f16.f16.f32 "
        "{%0,%1,%2,%3}, {%4,%5,%6,%7}, {%8,%9}, {%0,%1,%2,%3};"
        : "+f"(c[0]), "+f"(c[1]), "+f"(c[2]), "+f"(c[3])
        : "r"(a[0]), "r"(a[1]), "r"(a[2]), "r"(a[3]), "r"(b[0]), "r"(b[1]));
}
__device__ __forceinline__ void split2(float x, float y, uint32_t& hi, uint32_t& lo) {
    __nv_bfloat16 hx = __float2bfloat16(x), hy = __float2bfloat16(y);
    __nv_bfloat162 hh; hh.x = hx; hh.y = hy;
    __nv_bfloat162 ll;
    ll.x = __float2bfloat16(x - __bfloat162float(hx));
    ll.y = __float2bfloat16(y - __bfloat162float(hy));
    hi = *reinterpret_cast<uint32_t*>(&hh);
    lo = *reinterpret_cast<uint32_t*>(&ll);
}

// ---------------- fp32 -> fp16 convert ----------------
__global__ void to_f16(const float4* __restrict__ src, __half2* __restrict__ dst, int n4) {
    int i = blockIdx.x * blockDim.x + threadIdx.x;
    if (i >= n4) return;
    float4 v = src[i];
    dst[2 * i]     = __floats2half2_rn(v.x, v.y);
    dst[2 * i + 1] = __floats2half2_rn(v.z, v.w);
}

// ---------------- transpose + split: W[K,N] fp32 -> T[N,K] (hi, lo) fp16 ----------------
__global__ void transpose_split_h(const float* __restrict__ W, __half* __restrict__ Th,
                                  __half* __restrict__ Tl, int K, int N) {
    __shared__ float t[32][33];
    int k0 = blockIdx.y * 32, n0 = blockIdx.x * 32;
    int tx = threadIdx.x, ty = threadIdx.y;
#pragma unroll
    for (int j = 0; j < 4; j++)
        t[ty + j * 8][tx] = W[(size_t)(k0 + ty + j * 8) * N + n0 + tx];
    __syncthreads();
#pragma unroll
    for (int j = 0; j < 4; j++) {
        int n = n0 + ty + j * 8;
        float v = t[tx][ty + j * 8];
        __half h = __float2half_rn(v);
        Th[(size_t)n * K + k0 + tx] = h;
        Tl[(size_t)n * K + k0 + tx] = __float2half_rn(v - __half2float(h));
    }
}

// ---------------- fp16x2 tensor-core GEMM: C = A @ (Th + Tl)^T ----------------
#define GBM 128
#define GBN 128
#define GBK 32
#define LDT 40
#define TILE_E (GBM * LDT)
#define STAGE_E (3 * TILE_E)          // A, Bh, Bl
#define GSM_BYTES (2 * STAGE_E * 2)   // 61440

__global__ __launch_bounds__(256, 1)
void gemm_tc(const __half* __restrict__ A,
             const __half* __restrict__ Bh, const __half* __restrict__ Bl,
             float* __restrict__ C, int M, int N, int K)
{
    extern __shared__ __half sm[];
    const uint32_t sb = smem_u32(sm);
    const int tid = threadIdx.x;
    const int wid = tid / 32, lane = tid % 32;
    const int warp_m = wid % 4;
    const int warp_n = wid / 4;
    const int m0 = blockIdx.y * GBM, n0 = blockIdx.x * GBN;

    const int ld_row = tid / 4;
    const int ld_col = (tid % 4) * 8;

    const __half* pA  = A  + (size_t)(m0 + ld_row) * K + ld_col;
    const __half* pBh = Bh + (size_t)(n0 + ld_row) * K + ld_col;
    const __half* pBl = Bl + (size_t)(n0 + ld_row) * K + ld_col;
    const size_t rstep64 = (size_t)64 * K;

    auto load_chunk = [&](int t, int stg) {
        uint32_t sbase = sb + (uint32_t)(stg * STAGE_E) * 2u;
        uint32_t soff = ((uint32_t)ld_row * LDT + (uint32_t)ld_col) * 2u;
        const int kk = t * GBK;
#pragma unroll
        for (int j = 0; j < 2; j++) {
            uint32_t so = soff + (uint32_t)(j * 64 * LDT) * 2u;
            cp_async16(sbase + 0 * TILE_E * 2 + so, pA  + kk + j * rstep64);
            cp_async16(sbase + 1 * TILE_E * 2 + so, pBh + kk + j * rstep64);
            cp_async16(sbase + 2 * TILE_E * 2 + so, pBl + kk + j * rstep64);
        }
    };

    float acc[2][8][4];
#pragma unroll
    for (int i = 0; i < 2; i++)
#pragma unroll
        for (int j = 0; j < 8; j++)
#pragma unroll
            for (int r = 0; r < 4; r++) acc[i][j][r] = 0.f;

    const int nch = K / GBK;
    load_chunk(0, 0);
    cp_commit();

    for (int t = 0; t < nch; t++) {
        const int stg = t & 1;
        if (t + 1 < nch) {
            load_chunk(t + 1, stg ^ 1);
            cp_commit();
            cp_wait<1>();
        } else {
            cp_wait<0>();
        }
        __syncthreads();

        const uint32_t sbase = sb + (uint32_t)(stg * STAGE_E) * 2u;
#pragma unroll
        for (int ks = 0; ks < 2; ks++) {
            const uint32_t kc = (uint32_t)(ks * 16 + (lane / 16) * 8);
            uint32_t ah[2][4];
#pragma unroll
            for (int mt = 0; mt < 2; mt++) {
                uint32_t row = (uint32_t)(warp_m * 32 + mt * 16 + (lane % 16));
                uint32_t off = (row * LDT + kc) * 2u;
                ldsm_x4(ah[mt], sbase + 0 * TILE_E * 2 + off);
            }
            uint32_t bh[8][2], bl[8][2];
#pragma unroll
            for (int ng = 0; ng < 4; ng++) {
                uint32_t row = (uint32_t)(warp_n * 64 + ng * 16 + (lane % 8) +
                                          ((lane / 8) % 2) * 8);
                uint32_t off = (row * LDT + kc) * 2u;
                uint32_t r[4];
                ldsm_x4(r, sbase + 1 * TILE_E * 2 + off);
                bh[2 * ng][0] = r[0]; bh[2 * ng][1] = r[2];
                bh[2 * ng + 1][0] = r[1]; bh[2 * ng + 1][1] = r[3];
                ldsm_x4(r, sbase + 2 * TILE_E * 2 + off);
                bl[2 * ng][0] = r[0]; bl[2 * ng][1] = r[2];
                bl[2 * ng + 1][0] = r[1]; bl[2 * ng + 1][1] = r[3];
            }
#pragma unroll
            for (int mt = 0; mt < 2; mt++)
#pragma unroll
                for (int nt = 0; nt < 8; nt++) {
                    mma_f16(acc[mt][nt], ah[mt], bh[nt]);
                    mma_f16(acc[mt][nt], ah[mt], bl[nt]);
                }
        }
        __syncthreads();
    }

#pragma unroll
    for (int mt = 0; mt < 2; mt++) {
        int row = m0 + warp_m * 32 + mt * 16 + lane / 4;
#pragma unroll
        for (int nt = 0; nt < 8; nt++) {
            int col = n0 + warp_n * 64 + nt * 8 + (lane % 4) * 2;
            float2 v0 = make_float2(acc[mt][nt][0], acc[mt][nt][1]);
            float2 v1 = make_float2(acc[mt][nt][2], acc[mt][nt][3]);
            *reinterpret_cast<float2*>(&C[(size_t)row * N + col]) = v0;
            *reinterpret_cast<float2*>(&C[(size_t)(row + 8) * N + col]) = v1;
        }
    }
}

// ---------------- RoPE + scale + split, Q: [b,s,h,d] f32 -> [b,h,s,d] hi/lo ----------------
__global__ void rope_split_q(const float* __restrict__ q, const float* __restrict__ fc,
                             __nv_bfloat16* __restrict__ qh, __nv_bfloat16* __restrict__ ql) {
    int idx = blockIdx.x * blockDim.x + threadIdx.x;
    if (idx >= B * H * S * (D / 2)) return;
    int i = idx % (D / 2);
    int s = (idx / (D / 2)) % S;
    int h = (idx / (D / 2) / S) % H;
    int b = idx / (D / 2) / S / H;
    float c  = fc[(s * (D / 2) + i) * 2 + 0];
    float sn = fc[(s * (D / 2) + i) * 2 + 1];
    const float* p = q + ((size_t)(b * S + s) * H + h) * D + 2 * i;
    float x0 = p[0], x1 = p[1];
    float r0 = (x0 * c - x1 * sn) * QK_SCALE;
    float r1 = (x0 * sn + x1 * c) * QK_SCALE;
    __nv_bfloat16 h0 = __float2bfloat16(r0), h1 = __float2bfloat16(r1);
    size_t o = ((size_t)(b * H + h) * S + s) * D + 2 * i;
    *reinterpret_cast<__nv_bfloat162*>(qh + o) = __halves2bfloat162(h0, h1);
    *reinterpret_cast<__nv_bfloat162*>(ql + o) =
        __halves2bfloat162(__float2bfloat16(r0 - __bfloat162float(h0)),
                           __float2bfloat16(r1 - __bfloat162float(h1)));
}

// ---------------- RoPE + split, K: [b,s,kvh,d] f32 -> [b,kvh,s,d] hi/lo ----------------
__global__ void rope_split_k(const float* __restrict__ k, const float* __restrict__ fc,
                             __nv_bfloat16* __restrict__ kh, __nv_bfloat16* __restrict__ kl) {
    int idx = blockIdx.x * blockDim.x + threadIdx.x;
    if (idx >= B * KVH * S * (D / 2)) return;
    int i = idx % (D / 2);
    int s = (idx / (D / 2)) % S;
    int h = (idx / (D / 2) / S) % KVH;
    int b = idx / (D / 2) / S / KVH;
    float c  = fc[(s * (D / 2) + i) * 2 + 0];
    float sn = fc[(s * (D / 2) + i) * 2 + 1];
    const float* p = k + ((size_t)(b * S + s) * KVH + h) * D + 2 * i;
    float x0 = p[0], x1 = p[1];
    float r0 = x0 * c - x1 * sn;
    float r1 = x0 * sn + x1 * c;
    __nv_bfloat16 h0 = __float2bfloat16(r0), h1 = __float2bfloat16(r1);
    size_t o = ((size_t)(b * KVH + h) * S + s) * D + 2 * i;
    *reinterpret_cast<__nv_bfloat162*>(kh + o) = __halves2bfloat162(h0, h1);
    *reinterpret_cast<__nv_bfloat162*>(kl + o) =
        __halves2bfloat162(__float2bfloat16(r0 - __bfloat162float(h0)),
                           __float2bfloat16(r1 - __bfloat162float(h1)));
}

// ---------------- V transpose + split: [b,s,kvh,d] f32 -> [b,kvh,d,s] hi/lo ----------------
__global__ void v_split_t(const float* __restrict__ v, __nv_bfloat16* __restrict__ vh,
                          __nv_bfloat16* __restrict__ vl) {
    __shared__ float t[32][33];
    int d0 = blockIdx.x * 32, s0 = blockIdx.y * 32;
    int bk = blockIdx.z;
    int b = bk / KVH, kvh = bk % KVH;
    int tx = threadIdx.x, ty = threadIdx.y;
#pragma unroll
    for (int j = 0; j < 4; j++)
        t[ty + j * 8][tx] = v[((size_t)(b * S + s0 + ty + j * 8) * KVH + kvh) * D + d0 + tx];
    __syncthreads();
#pragma unroll
    for (int j = 0; j < 4; j++) {
        int d = d0 + ty + j * 8;
        float val = t[tx][ty + j * 8];
        __nv_bfloat16 h = __float2bfloat16(val);
        size_t o = ((size_t)(b * KVH + kvh) * D + d) * S + s0 + tx;
        vh[o] = h;
        vl[o] = __float2bfloat16(val - __bfloat162float(h));
    }
}

// ---------------- tensor-core flash attention (bf16x3), causal, GQA ----------------
#define AM 128
#define AN 64
#define LQ 136
#define LV 72
#define SQH 0
#define SQL 17408
#define SST 34816
#define STSZ 35840
#define OKL 8704
#define OVH 17408
#define OVL 26624
#define ATT_SMEM ((SST + 2 * STSZ) * 2)   // 212992 bytes

__global__ __launch_bounds__(256, 1)
void attn_tc(const __nv_bfloat16* __restrict__ Qh, const __nv_bfloat16* __restrict__ Ql,
             const __nv_bfloat16* __restrict__ Kh, const __nv_bfloat16* __restrict__ Kl,
             const __nv_bfloat16* __restrict__ Vh, const __nv_bfloat16* __restrict__ Vl,
             __half* __restrict__ Oh)
{
    extern __shared__ __nv_bfloat16 sma[];
    const uint32_t sb = smem_u32(sma);
    const int tid = threadIdx.x, wid = tid / 32, lane = tid % 32;
    const int bx = blockIdx.x, h = blockIdx.y, b = blockIdx.z;
    const int kvh = h / GROUPS;
    const int q0 = bx * AM;

    const __nv_bfloat16* qhp = Qh + ((size_t)(b * H + h) * S + q0) * D;
    const __nv_bfloat16* qlp = Ql + ((size_t)(b * H + h) * S + q0) * D;
    const __nv_bfloat16* khp = Kh + (size_t)(b * KVH + kvh) * S * D;
    const __nv_bfloat16* klp = Kl + (size_t)(b * KVH + kvh) * S * D;
    const __nv_bfloat16* vhp = Vh + (size_t)(b * KVH + kvh) * D * S;
    const __nv_bfloat16* vlp = Vl + (size_t)(b * KVH + kvh) * D * S;

#pragma unroll
    for (int j = 0; j < 8; j++) {
        int seg = tid + j * 256;
        int row = seg >> 4, c = (seg & 15) * 8;
        cp_async16(sb + (uint32_t)(SQH + row * LQ + c) * 2, qhp + (size_t)row * D + c);
        cp_async16(sb + (uint32_t)(SQL + row * LQ + c) * 2, qlp + (size_t)row * D + c);
    }
    cp_commit();

    auto load_kv = [&](int t, int stg) {
        uint32_t sbase = sb + (uint32_t)(SST + stg * STSZ) * 2;
        int kv0 = t * AN;
#pragma unroll
        for (int j = 0; j < 4; j++) {
            int seg = tid + j * 256;
            int row = seg >> 4, c = (seg & 15) * 8;
            cp_async16(sbase + (uint32_t)(row * LQ + c) * 2,
                       khp + (size_t)(kv0 + row) * D + c);
            cp_async16(sbase + (uint32_t)(OKL + row * LQ + c) * 2,
                       klp + (size_t)(kv0 + row) * D + c);
        }
#pragma unroll
        for (int j = 0; j < 4; j++) {
            int seg = tid + j * 256;
            int row = seg >> 3, c = (seg & 7) * 8;
            cp_async16(sbase + (uint32_t)(OVH + row * LV + c) * 2,
                       vhp + (size_t)row * S + kv0 + c);
            cp_async16(sbase + (uint32_t)(OVL + row * LV + c) * 2,
                       vlp + (size_t)row * S + kv0 + c);
        }
    };

    float m0 = -1e30f, m1 = -1e30f, l0 = 0.f, l1 = 0.f;
    float oacc[16][4];
#pragma unroll
    for (int i = 0; i < 16; i++)
#pragma unroll
        for (int j = 0; j < 4; j++) oacc[i][j] = 0.f;

    const int ntiles = 2 * (bx + 1);
    load_kv(0, 0);
    cp_commit();

    for (int t = 0; t < ntiles; t++) {
        if (t + 1 < ntiles) {
            load_kv(t + 1, (t + 1) & 1);
            cp_commit();
            cp_wait<1>();
        } else {
            cp_wait<0>();
        }
        __syncthreads();
        const uint32_t stg = sb + (uint32_t)(SST + (t & 1) * STSZ) * 2;

        float sacc[8][4];
#pragma unroll
        for (int i = 0; i < 8; i++)
#pragma unroll
            for (int j = 0; j < 4; j++) sacc[i][j] = 0.f;

#pragma unroll
        for (int ks = 0; ks < 8; ks++) {
            const uint32_t kc = (uint32_t)(ks * 16 + (lane >> 4) * 8);
            uint32_t ah[4], al[4];
            const uint32_t qrow = (uint32_t)(wid * 16 + (lane & 15));
            ldsm_x4(ah, sb + (SQH + qrow * LQ + kc) * 2);
            ldsm_x4(al, sb + (SQL + qrow * LQ + kc) * 2);
            const uint32_t brow = (uint32_t)((lane & 7) + ((lane >> 3) & 1) * 8);
#pragma unroll
            for (int ng = 0; ng < 4; ng++) {
                uint32_t row = (uint32_t)(ng * 16) + brow;
                uint32_t rh[4], rl[4];
                ldsm_x4(rh, stg + (row * LQ + kc) * 2);
                ldsm_x4(rl, stg + (OKL + row * LQ + kc) * 2);
                uint32_t b0[2] = {rh[0], rh[2]}, b1[2] = {rh[1], rh[3]};
                uint32_t bl0[2] = {rl[0], rl[2]}, bl1[2] = {rl[1], rl[3]};
                mma_bf16(sacc[2 * ng],     ah, b0);
                mma_bf16(sacc[2 * ng],     ah, bl0);
                mma_bf16(sacc[2 * ng],     al, b0);
                mma_bf16(sacc[2 * ng + 1], ah, b1);
                mma_bf16(sacc[2 * ng + 1], ah, bl1);
                mma_bf16(sacc[2 * ng + 1], al, b1);
            }
        }

        const int row0 = q0 + wid * 16 + (lane >> 2);
        if (t >= 2 * bx) {
            const int kvb = t * AN + 2 * (lane & 3);
#pragma unroll
            for (int nt = 0; nt < 8; nt++) {
                int col = kvb + nt * 8;
                if (col     > row0)     sacc[nt][0] = -1e30f;
                if (col + 1 > row0)     sacc[nt][1] = -1e30f;
                if (col     > row0 + 8) sacc[nt][2] = -1e30f;
                if (col + 1 > row0 + 8) sacc[nt][3] = -1e30f;
            }
        }

        float mx0 = -1e30f, mx1 = -1e30f;
#pragma unroll
        for (int nt = 0; nt < 8; nt++) {
            mx0 = fmaxf(mx0, fmaxf(sacc[nt][0], sacc[nt][1]));
            mx1 = fmaxf(mx1, fmaxf(sacc[nt][2], sacc[nt][3]));
        }
        mx0 = fmaxf(mx0, __shfl_xor_sync(0xffffffffu, mx0, 1));
        mx0 = fmaxf(mx0, __shfl_xor_sync(0xffffffffu, mx0, 2));
        mx1 = fmaxf(mx1, __shfl_xor_sync(0xffffffffu, mx1, 1));
        mx1 = fmaxf(mx1, __shfl_xor_sync(0xffffffffu, mx1, 2));
        float nm0 = fmaxf(m0, mx0), nm1 = fmaxf(m1, mx1);
        float f0 = __expf(m0 - nm0), f1 = __expf(m1 - nm1);
        float sum0 = 0.f, sum1 = 0.f;
#pragma unroll
        for (int nt = 0; nt < 8; nt++) {
            sacc[nt][0] = __expf(sacc[nt][0] - nm0);
            sacc[nt][1] = __expf(sacc[nt][1] - nm0);
            sacc[nt][2] = __expf(sacc[nt][2] - nm1);
            sacc[nt][3] = __expf(sacc[nt][3] - nm1);
            sum0 += sacc[nt][0] + sacc[nt][1];
            sum1 += sacc[nt][2] + sacc[nt][3];
        }
        sum0 += __shfl_xor_sync(0xffffffffu, sum0, 1);
        sum0 += __shfl_xor_sync(0xffffffffu, sum0, 2);
        sum1 += __shfl_xor_sync(0xffffffffu, sum1, 1);
        sum1 += __shfl_xor_sync(0xffffffffu, sum1, 2);
        l0 = l0 * f0 + sum0;
        l1 = l1 * f1 + sum1;
        m0 = nm0;
        m1 = nm1;
#pragma unroll
        for (int nt = 0; nt < 16; nt++) {
            oacc[nt][0] *= f0;
            oacc[nt][1] *= f0;
            oacc[nt][2] *= f1;
            oacc[nt][3] *= f1;
        }

#pragma unroll
        for (int ks2 = 0; ks2 < 4; ks2++) {
            const float* ce = sacc[2 * ks2];
            const float* co = sacc[2 * ks2 + 1];
            uint32_t ph[4], pl[4];
            split2(ce[0], ce[1], ph[0], pl[0]);
            split2(ce[2], ce[3], ph[1], pl[1]);
            split2(co[0], co[1], ph[2], pl[2]);
            split2(co[2], co[3], ph[3], pl[3]);
            const uint32_t kc2 = (uint32_t)(ks2 * 16 + (lane >> 4) * 8);
            const uint32_t brow = (uint32_t)((lane & 7) + ((lane >> 3) & 1) * 8);
#pragma unroll
            for (int ng = 0; ng < 8; ng++) {
                uint32_t row = (uint32_t)(ng * 16) + brow;
                uint32_t rh[4], rl[4];
                ldsm_x4(rh, stg + (OVH + row * LV + kc2) * 2);
                ldsm_x4(rl, stg + (OVL + row * LV + kc2) * 2);
                uint32_t b0[2] = {rh[0], rh[2]}, b1[2] = {rh[1], rh[3]};
                uint32_t bl0[2] = {rl[0], rl[2]}, bl1[2] = {rl[1], rl[3]};
                mma_bf16(oacc[2 * ng],     ph, b0);
                mma_bf16(oacc[2 * ng],     pl, b0);
                mma_bf16(oacc[2 * ng],     ph, bl0);
                mma_bf16(oacc[2 * ng + 1], ph, b1);
                mma_bf16(oacc[2 * ng + 1], pl, b1);
                mma_bf16(oacc[2 * ng + 1], ph, bl1);
            }
        }
        __syncthreads();
    }

    // ---- epilogue: normalize, store fp16 O in [b,s,h,d] ----
    const float inv0 = 1.f / l0, inv1 = 1.f / l1;
    const int row0 = q0 + wid * 16 + (lane >> 2);
#pragma unroll
    for (int nt = 0; nt < 16; nt++) {
        int col = nt * 8 + 2 * (lane & 3);
        size_t o0 = ((size_t)(b * S + row0) * H + h) * D + col;
        size_t o1 = ((size_t)(b * S + row0 + 8) * H + h) * D + col;
        *reinterpret_cast<__half2*>(Oh + o0) =
            __floats2half2_rn(oacc[nt][0] * inv0, oacc[nt][1] * inv0);
        *reinterpret_cast<__half2*>(Oh + o1) =
            __floats2half2_rn(oacc[nt][2] * inv1, oacc[nt][3] * inv1);
    }
}

// ---------------- host ----------------
extern "C" void kernel_launch(void* const* d_in, const int* in_sizes, int n_in,
                              void* d_out, int out_size)
{
    const float* x  = (const float*)d_in[0];
    const float* fc = (const float*)d_in[1];
    const float* wq = (const float*)d_in[2];
    const float* wk = (const float*)d_in[3];
    const float* wv = (const float*)d_in[4];
    const float* wo = (const float*)d_in[5];
    float* out = (float*)d_out;

    float *pq, *pk, *pv;
    cudaGetSymbolAddress((void**)&pq, g_q);
    cudaGetSymbolAddress((void**)&pk, g_k);
    cudaGetSymbolAddress((void**)&pv, g_v);
    __half *xa_h, *oa_h;
    __half *wqT_h, *wqT_l, *wkT_h, *wkT_l, *wvT_h, *wvT_l, *woT_h, *woT_l;
    __nv_bfloat16 *qs_hi, *qs_lo, *ks_hi, *ks_lo, *vt_hi, *vt_lo;
    cudaGetSymbolAddress((void**)&xa_h, g_xa_h);
    cudaGetSymbolAddress((void**)&oa_h, g_oa_h);
    cudaGetSymbolAddress((void**)&wqT_h, g_wqT_h);
    cudaGetSymbolAddress((void**)&wqT_l, g_wqT_l);
    cudaGetSymbolAddress((void**)&wkT_h, g_wkT_h);
    cudaGetSymbolAddress((void**)&wkT_l, g_wkT_l);
    cudaGetSymbolAddress((void**)&wvT_h, g_wvT_h);
    cudaGetSymbolAddress((void**)&wvT_l, g_wvT_l);
    cudaGetSymbolAddress((void**)&woT_h, g_woT_h);
    cudaGetSymbolAddress((void**)&woT_l, g_woT_l);
    cudaGetSymbolAddress((void**)&qs_hi, g_qs_hi);
    cudaGetSymbolAddress((void**)&qs_lo, g_qs_lo);
    cudaGetSymbolAddress((void**)&ks_hi, g_ks_hi);
    cudaGetSymbolAddress((void**)&ks_lo, g_ks_lo);
    cudaGetSymbolAddress((void**)&vt_hi, g_vt_hi);
    cudaGetSymbolAddress((void**)&vt_lo, g_vt_lo);

    cudaFuncSetAttribute(gemm_tc, cudaFuncAttributeMaxDynamicSharedMemorySize, GSM_BYTES);
    cudaFuncSetAttribute(attn_tc, cudaFuncAttributeMaxDynamicSharedMemorySize, ATT_SMEM);

    // x -> fp16
    {
        int n4 = MROWS * HID / 4;
        to_f16<<<(n4 + 255) / 256, 256>>>((const float4*)x, (__half2*)xa_h, n4);
    }
    // transpose + split weights (fp16 hi/lo)
    {
        dim3 blk(32, 8);
        transpose_split_h<<<dim3(ND_Q / 32, HID / 32), blk>>>(wq, wqT_h, wqT_l, HID, ND_Q);
        transpose_split_h<<<dim3(ND_KV / 32, HID / 32), blk>>>(wk, wkT_h, wkT_l, HID, ND_KV);
        transpose_split_h<<<dim3(ND_KV / 32, HID / 32), blk>>>(wv, wvT_h, wvT_l, HID, ND_KV);
        transpose_split_h<<<dim3(ND_Q / 32, ND_Q / 32), blk>>>(wo, woT_h, woT_l, ND_Q, HID);
    }
    // QKV projections (fp16x2 tensor cores)
    {
        gemm_tc<<<dim3(ND_Q / GBN, MROWS / GBM), 256, GSM_BYTES>>>(
            xa_h, wqT_h, wqT_l, pq, MROWS, ND_Q, HID);
        gemm_tc<<<dim3(ND_KV / GBN, MROWS / GBM), 256, GSM_BYTES>>>(
            xa_h, wkT_h, wkT_l, pk, MROWS, ND_KV, HID);
        gemm_tc<<<dim3(ND_KV / GBN, MROWS / GBM), 256, GSM_BYTES>>>(
            xa_h, wvT_h, wvT_l, pv, MROWS, ND_KV, HID);
    }
    // RoPE + split + relayout for attention
    {
        int nq = B * H * S * (D / 2);
        rope_split_q<<<(nq + 255) / 256, 256>>>(pq, fc, qs_hi, qs_lo);
        int nk = B * KVH * S * (D / 2);
        rope_split_k<<<(nk + 255) / 256, 256>>>(pk, fc, ks_hi, ks_lo);
        dim3 blk(32, 8);
        v_split_t<<<dim3(D / 32, S / 32, B * KVH), blk>>>(pv, vt_hi, vt_lo);
    }
    // tensor-core flash attention (writes fp16 O directly)
    {
        dim3 grid(S / AM, H, B);
        attn_tc<<<grid, 256, ATT_SMEM>>>(qs_hi, qs_lo, ks_hi, ks_lo, vt_hi, vt_lo, oa_h);
    }
    // output projection (fp16x2 tensor cores)
    {
        gemm_tc<<<dim3(HID / GBN, MROWS / GBM), 256, GSM_BYTES>>>(
            oa_h, woT_h, woT_l, out, MROWS, HID, ND_Q);
    }
}

// round 9
// speedup vs baseline: 4.1364x; 1.1098x over previous
#include <cuda_runtime.h>
#include <cuda_bf16.h>
#include <cuda_fp16.h>
#include <cstdint>

#define B 2
#define S 2048
#define HID 2048
#define H 16
#define KVH 4
#define D 128
#define GROUPS (H / KVH)
#define MROWS (B * S)          // 4096
#define ND_Q (H * D)           // 2048
#define ND_KV (KVH * D)        // 512
#define QK_SCALE 0.08838834764831845f

// ---------------- scratch (no allocations allowed) ----------------
__device__ float g_q[MROWS * H * D];
__device__ float g_k[MROWS * KVH * D];
__device__ float g_v[MROWS * KVH * D];

__device__ __align__(16) __half g_xa_h[MROWS * HID];      // x as fp16
__device__ __align__(16) __half g_oa_h[MROWS * ND_Q];     // attention out as fp16
__device__ __align__(16) __half g_wqT_h[ND_Q * HID];
__device__ __align__(16) __half g_wqT_l[ND_Q * HID];
__device__ __align__(16) __half g_wkT_h[ND_KV * HID];
__device__ __align__(16) __half g_wkT_l[ND_KV * HID];
__device__ __align__(16) __half g_wvT_h[ND_KV * HID];
__device__ __align__(16) __half g_wvT_l[ND_KV * HID];
__device__ __align__(16) __half g_woT_h[HID * ND_Q];
__device__ __align__(16) __half g_woT_l[HID * ND_Q];
// attention operand layouts (fp16x2 path)
__device__ __align__(16) __half g_qs_h[B * H * S * D];    // [b][h][s][d], scaled
__device__ __align__(16) __half g_ks_h[B * KVH * S * D];  // [b][kvh][s][d]
__device__ __align__(16) __half g_ks_l[B * KVH * S * D];
__device__ __align__(16) __half g_vt_h[B * KVH * D * S];  // [b][kvh][d][s]

// ---------------- helpers ----------------
__device__ __forceinline__ uint32_t smem_u32(const void* p) {
    uint32_t a;
    asm("{ .reg .u64 t; cvta.to.shared.u64 t, %1; cvt.u32.u64 %0, t; }" : "=r"(a) : "l"(p));
    return a;
}
__device__ __forceinline__ void cp_async16(uint32_t saddr, const void* gaddr) {
    asm volatile("cp.async.cg.shared.global [%0], [%1], 16;" :: "r"(saddr), "l"(gaddr)
                 : "memory");
}
__device__ __forceinline__ void cp_commit() {
    asm volatile("cp.async.commit_group;" ::: "memory");
}
template <int N>
__device__ __forceinline__ void cp_wait() {
    asm volatile("cp.async.wait_group %0;" :: "n"(N) : "memory");
}
__device__ __forceinline__ void ldsm_x4(uint32_t* r, uint32_t addr) {
    asm volatile("ldmatrix.sync.aligned.m8n8.x4.shared.b16 {%0,%1,%2,%3}, [%4];"
                 : "=r"(r[0]), "=r"(r[1]), "=r"(r[2]), "=r"(r[3]) : "r"(addr));
}
__device__ __forceinline__ void mma_f16(float* c, const uint32_t* a, const uint32_t* b) {
    asm volatile(
        "mma.sync.aligned.m16n8k16.row.col.f32.f16.f16.f32 "
        "{%0,%1,%2,%3}, {%4,%5,%6,%7}, {%8,%9}, {%0,%1,%2,%3};"
        : "+f"(c[0]), "+f"(c[1]), "+f"(c[2]), "+f"(c[3])
        : "r"(a[0]), "r"(a[1]), "r"(a[2]), "r"(a[3]), "r"(b[0]), "r"(b[1]));
}
// fp32 pair -> fp16 (hi, lo) packed
__device__ __forceinline__ void split2h(float x, float y, uint32_t& hi, uint32_t& lo) {
    __half hx = __float2half_rn(x), hy = __float2half_rn(y);
    __half2 hh; hh.x = hx; hh.y = hy;
    __half2 ll;
    ll.x = __float2half_rn(x - __half2float(hx));
    ll.y = __float2half_rn(y - __half2float(hy));
    hi = *reinterpret_cast<uint32_t*>(&hh);
    lo = *reinterpret_cast<uint32_t*>(&ll);
}

// ---------------- fp32 -> fp16 convert ----------------
__global__ void to_f16(const float4* __restrict__ src, __half2* __restrict__ dst, int n4) {
    int i = blockIdx.x * blockDim.x + threadIdx.x;
    if (i >= n4) return;
    float4 v = src[i];
    dst[2 * i]     = __floats2half2_rn(v.x, v.y);
    dst[2 * i + 1] = __floats2half2_rn(v.z, v.w);
}

// ---------------- transpose + split: W[K,N] fp32 -> T[N,K] (hi, lo) fp16 ----------------
__global__ void transpose_split_h(const float* __restrict__ W, __half* __restrict__ Th,
                                  __half* __restrict__ Tl, int K, int N) {
    __shared__ float t[32][33];
    int k0 = blockIdx.y * 32, n0 = blockIdx.x * 32;
    int tx = threadIdx.x, ty = threadIdx.y;
#pragma unroll
    for (int j = 0; j < 4; j++)
        t[ty + j * 8][tx] = W[(size_t)(k0 + ty + j * 8) * N + n0 + tx];
    __syncthreads();
#pragma unroll
    for (int j = 0; j < 4; j++) {
        int n = n0 + ty + j * 8;
        float v = t[tx][ty + j * 8];
        __half h = __float2half_rn(v);
        Th[(size_t)n * K + k0 + tx] = h;
        Tl[(size_t)n * K + k0 + tx] = __float2half_rn(v - __half2float(h));
    }
}

// ---------------- fp16x2 tensor-core GEMM: C = A @ (Th + Tl)^T ----------------
#define GBM 128
#define GBN 128
#define GBK 32
#define LDT 40
#define TILE_E (GBM * LDT)
#define STAGE_E (3 * TILE_E)          // A, Bh, Bl
#define GSM_BYTES (2 * STAGE_E * 2)   // 61440

__global__ __launch_bounds__(256, 1)
void gemm_tc(const __half* __restrict__ A,
             const __half* __restrict__ Bh, const __half* __restrict__ Bl,
             float* __restrict__ C, int M, int N, int K)
{
    extern __shared__ __half sm[];
    const uint32_t sb = smem_u32(sm);
    const int tid = threadIdx.x;
    const int wid = tid / 32, lane = tid % 32;
    const int warp_m = wid % 4;
    const int warp_n = wid / 4;
    const int m0 = blockIdx.y * GBM, n0 = blockIdx.x * GBN;

    const int ld_row = tid / 4;
    const int ld_col = (tid % 4) * 8;

    const __half* pA  = A  + (size_t)(m0 + ld_row) * K + ld_col;
    const __half* pBh = Bh + (size_t)(n0 + ld_row) * K + ld_col;
    const __half* pBl = Bl + (size_t)(n0 + ld_row) * K + ld_col;
    const size_t rstep64 = (size_t)64 * K;

    auto load_chunk = [&](int t, int stg) {
        uint32_t sbase = sb + (uint32_t)(stg * STAGE_E) * 2u;
        uint32_t soff = ((uint32_t)ld_row * LDT + (uint32_t)ld_col) * 2u;
        const int kk = t * GBK;
#pragma unroll
        for (int j = 0; j < 2; j++) {
            uint32_t so = soff + (uint32_t)(j * 64 * LDT) * 2u;
            cp_async16(sbase + 0 * TILE_E * 2 + so, pA  + kk + j * rstep64);
            cp_async16(sbase + 1 * TILE_E * 2 + so, pBh + kk + j * rstep64);
            cp_async16(sbase + 2 * TILE_E * 2 + so, pBl + kk + j * rstep64);
        }
    };

    float acc[2][8][4];
#pragma unroll
    for (int i = 0; i < 2; i++)
#pragma unroll
        for (int j = 0; j < 8; j++)
#pragma unroll
            for (int r = 0; r < 4; r++) acc[i][j][r] = 0.f;

    const int nch = K / GBK;
    load_chunk(0, 0);
    cp_commit();

    for (int t = 0; t < nch; t++) {
        const int stg = t & 1;
        if (t + 1 < nch) {
            load_chunk(t + 1, stg ^ 1);
            cp_commit();
            cp_wait<1>();
        } else {
            cp_wait<0>();
        }
        __syncthreads();

        const uint32_t sbase = sb + (uint32_t)(stg * STAGE_E) * 2u;
#pragma unroll
        for (int ks = 0; ks < 2; ks++) {
            const uint32_t kc = (uint32_t)(ks * 16 + (lane / 16) * 8);
            uint32_t ah[2][4];
#pragma unroll
            for (int mt = 0; mt < 2; mt++) {
                uint32_t row = (uint32_t)(warp_m * 32 + mt * 16 + (lane % 16));
                uint32_t off = (row * LDT + kc) * 2u;
                ldsm_x4(ah[mt], sbase + 0 * TILE_E * 2 + off);
            }
            uint32_t bh[8][2], bl[8][2];
#pragma unroll
            for (int ng = 0; ng < 4; ng++) {
                uint32_t row = (uint32_t)(warp_n * 64 + ng * 16 + (lane % 8) +
                                          ((lane / 8) % 2) * 8);
                uint32_t off = (row * LDT + kc) * 2u;
                uint32_t r[4];
                ldsm_x4(r, sbase + 1 * TILE_E * 2 + off);
                bh[2 * ng][0] = r[0]; bh[2 * ng][1] = r[2];
                bh[2 * ng + 1][0] = r[1]; bh[2 * ng + 1][1] = r[3];
                ldsm_x4(r, sbase + 2 * TILE_E * 2 + off);
                bl[2 * ng][0] = r[0]; bl[2 * ng][1] = r[2];
                bl[2 * ng + 1][0] = r[1]; bl[2 * ng + 1][1] = r[3];
            }
#pragma unroll
            for (int mt = 0; mt < 2; mt++)
#pragma unroll
                for (int nt = 0; nt < 8; nt++) {
                    mma_f16(acc[mt][nt], ah[mt], bh[nt]);
                    mma_f16(acc[mt][nt], ah[mt], bl[nt]);
                }
        }
        __syncthreads();
    }

#pragma unroll
    for (int mt = 0; mt < 2; mt++) {
        int row = m0 + warp_m * 32 + mt * 16 + lane / 4;
#pragma unroll
        for (int nt = 0; nt < 8; nt++) {
            int col = n0 + warp_n * 64 + nt * 8 + (lane % 4) * 2;
            float2 v0 = make_float2(acc[mt][nt][0], acc[mt][nt][1]);
            float2 v1 = make_float2(acc[mt][nt][2], acc[mt][nt][3]);
            *reinterpret_cast<float2*>(&C[(size_t)row * N + col]) = v0;
            *reinterpret_cast<float2*>(&C[(size_t)(row + 8) * N + col]) = v1;
        }
    }
}

// -------- RoPE + scale, Q: [b,s,h,d] f32 -> [b,h,s,d] fp16 --------
__global__ void rope_q_f16(const float* __restrict__ q, const float* __restrict__ fc,
                           __half* __restrict__ qh) {
    int idx = blockIdx.x * blockDim.x + threadIdx.x;
    if (idx >= B * H * S * (D / 2)) return;
    int i = idx % (D / 2);
    int s = (idx / (D / 2)) % S;
    int h = (idx / (D / 2) / S) % H;
    int b = idx / (D / 2) / S / H;
    float c  = fc[(s * (D / 2) + i) * 2 + 0];
    float sn = fc[(s * (D / 2) + i) * 2 + 1];
    const float* p = q + ((size_t)(b * S + s) * H + h) * D + 2 * i;
    float x0 = p[0], x1 = p[1];
    float r0 = (x0 * c - x1 * sn) * QK_SCALE;
    float r1 = (x0 * sn + x1 * c) * QK_SCALE;
    size_t o = ((size_t)(b * H + h) * S + s) * D + 2 * i;
    *reinterpret_cast<__half2*>(qh + o) = __floats2half2_rn(r0, r1);
}

// -------- RoPE + split, K: [b,s,kvh,d] f32 -> [b,kvh,s,d] fp16 hi/lo --------
__global__ void rope_k_f16(const float* __restrict__ k, const float* __restrict__ fc,
                           __half* __restrict__ kh, __half* __restrict__ kl) {
    int idx = blockIdx.x * blockDim.x + threadIdx.x;
    if (idx >= B * KVH * S * (D / 2)) return;
    int i = idx % (D / 2);
    int s = (idx / (D / 2)) % S;
    int h = (idx / (D / 2) / S) % KVH;
    int b = idx / (D / 2) / S / KVH;
    float c  = fc[(s * (D / 2) + i) * 2 + 0];
    float sn = fc[(s * (D / 2) + i) * 2 + 1];
    const float* p = k + ((size_t)(b * S + s) * KVH + h) * D + 2 * i;
    float x0 = p[0], x1 = p[1];
    float r0 = x0 * c - x1 * sn;
    float r1 = x0 * sn + x1 * c;
    __half h0 = __float2half_rn(r0), h1 = __float2half_rn(r1);
    size_t o = ((size_t)(b * KVH + h) * S + s) * D + 2 * i;
    __half2 hh; hh.x = h0; hh.y = h1;
    *reinterpret_cast<__half2*>(kh + o) = hh;
    *reinterpret_cast<__half2*>(kl + o) =
        __floats2half2_rn(r0 - __half2float(h0), r1 - __half2float(h1));
}

// -------- V transpose: [b,s,kvh,d] f32 -> [b,kvh,d,s] fp16 --------
__global__ void v_t_f16(const float* __restrict__ v, __half* __restrict__ vh) {
    __shared__ float t[32][33];
    int d0 = blockIdx.x * 32, s0 = blockIdx.y * 32;
    int bk = blockIdx.z;
    int b = bk / KVH, kvh = bk % KVH;
    int tx = threadIdx.x, ty = threadIdx.y;
#pragma unroll
    for (int j = 0; j < 4; j++)
        t[ty + j * 8][tx] = v[((size_t)(b * S + s0 + ty + j * 8) * KVH + kvh) * D + d0 + tx];
    __syncthreads();
#pragma unroll
    for (int j = 0; j < 4; j++) {
        int d = d0 + ty + j * 8;
        size_t o = ((size_t)(b * KVH + kvh) * D + d) * S + s0 + tx;
        vh[o] = __float2half_rn(t[tx][ty + j * 8]);
    }
}

// ---------------- tensor-core flash attention (fp16x2), causal, GQA ----------------
#define AM 128
#define AN 64
#define LQ 136
#define LV 72
#define SQH 0
#define SST 17408                 // start of KV stages (after Q)
#define STSZ 26624                // KH 8704 + KL 8704 + VH 9216
#define OKL 8704
#define OVH 17408
#define ATT_SMEM ((SST + 2 * STSZ) * 2)   // 141312 bytes

__global__ __launch_bounds__(256, 1)
void attn_tc(const __half* __restrict__ Qh,
             const __half* __restrict__ Kh, const __half* __restrict__ Kl,
             const __half* __restrict__ Vh,
             __half* __restrict__ Oh)
{
    extern __shared__ __half sma[];
    const uint32_t sb = smem_u32(sma);
    const int tid = threadIdx.x, wid = tid / 32, lane = tid % 32;
    const int bx = blockIdx.x, h = blockIdx.y, b = blockIdx.z;
    const int kvh = h / GROUPS;
    const int q0 = bx * AM;

    const __half* qhp = Qh + ((size_t)(b * H + h) * S + q0) * D;
    const __half* khp = Kh + (size_t)(b * KVH + kvh) * S * D;
    const __half* klp = Kl + (size_t)(b * KVH + kvh) * S * D;
    const __half* vhp = Vh + (size_t)(b * KVH + kvh) * D * S;

    // load Q tile (fp16): 128 rows x 128 cols
#pragma unroll
    for (int j = 0; j < 8; j++) {
        int seg = tid + j * 256;            // 0..2047
        int row = seg >> 4, c = (seg & 15) * 8;
        cp_async16(sb + (uint32_t)(SQH + row * LQ + c) * 2, qhp + (size_t)row * D + c);
    }
    cp_commit();

    auto load_kv = [&](int t, int stg) {
        uint32_t sbase = sb + (uint32_t)(SST + stg * STSZ) * 2;
        int kv0 = t * AN;
#pragma unroll
        for (int j = 0; j < 4; j++) {
            int seg = tid + j * 256;        // 0..1023
            int row = seg >> 4, c = (seg & 15) * 8;
            cp_async16(sbase + (uint32_t)(row * LQ + c) * 2,
                       khp + (size_t)(kv0 + row) * D + c);
            cp_async16(sbase + (uint32_t)(OKL + row * LQ + c) * 2,
                       klp + (size_t)(kv0 + row) * D + c);
        }
#pragma unroll
        for (int j = 0; j < 4; j++) {
            int seg = tid + j * 256;
            int row = seg >> 3, c = (seg & 7) * 8;
            cp_async16(sbase + (uint32_t)(OVH + row * LV + c) * 2,
                       vhp + (size_t)row * S + kv0 + c);
        }
    };

    float m0 = -1e30f, m1 = -1e30f, l0 = 0.f, l1 = 0.f;
    float oacc[16][4];
#pragma unroll
    for (int i = 0; i < 16; i++)
#pragma unroll
        for (int j = 0; j < 4; j++) oacc[i][j] = 0.f;

    const int ntiles = 2 * (bx + 1);
    load_kv(0, 0);
    cp_commit();

    for (int t = 0; t < ntiles; t++) {
        if (t + 1 < ntiles) {
            load_kv(t + 1, (t + 1) & 1);
            cp_commit();
            cp_wait<1>();
        } else {
            cp_wait<0>();
        }
        __syncthreads();
        const uint32_t stg = sb + (uint32_t)(SST + (t & 1) * STSZ) * 2;

        // ---- S = Q K^T (fp16x2: Qh * (Kh + Kl)) ----
        float sacc[8][4];
#pragma unroll
        for (int i = 0; i < 8; i++)
#pragma unroll
            for (int j = 0; j < 4; j++) sacc[i][j] = 0.f;

#pragma unroll
        for (int ks = 0; ks < 8; ks++) {
            const uint32_t kc = (uint32_t)(ks * 16 + (lane >> 4) * 8);
            uint32_t ah[4];
            const uint32_t qrow = (uint32_t)(wid * 16 + (lane & 15));
            ldsm_x4(ah, sb + (SQH + qrow * LQ + kc) * 2);
            const uint32_t brow = (uint32_t)((lane & 7) + ((lane >> 3) & 1) * 8);
#pragma unroll
            for (int ng = 0; ng < 4; ng++) {
                uint32_t row = (uint32_t)(ng * 16) + brow;
                uint32_t rh[4], rl[4];
                ldsm_x4(rh, stg + (row * LQ + kc) * 2);
                ldsm_x4(rl, stg + (OKL + row * LQ + kc) * 2);
                uint32_t b0[2] = {rh[0], rh[2]}, b1[2] = {rh[1], rh[3]};
                uint32_t bl0[2] = {rl[0], rl[2]}, bl1[2] = {rl[1], rl[3]};
                mma_f16(sacc[2 * ng],     ah, b0);
                mma_f16(sacc[2 * ng],     ah, bl0);
                mma_f16(sacc[2 * ng + 1], ah, b1);
                mma_f16(sacc[2 * ng + 1], ah, bl1);
            }
        }

        // ---- causal mask (only diagonal tiles) ----
        const int row0 = q0 + wid * 16 + (lane >> 2);
        if (t >= 2 * bx) {
            const int kvb = t * AN + 2 * (lane & 3);
#pragma unroll
            for (int nt = 0; nt < 8; nt++) {
                int col = kvb + nt * 8;
                if (col     > row0)     sacc[nt][0] = -1e30f;
                if (col + 1 > row0)     sacc[nt][1] = -1e30f;
                if (col     > row0 + 8) sacc[nt][2] = -1e30f;
                if (col + 1 > row0 + 8) sacc[nt][3] = -1e30f;
            }
        }

        // ---- online softmax ----
        float mx0 = -1e30f, mx1 = -1e30f;
#pragma unroll
        for (int nt = 0; nt < 8; nt++) {
            mx0 = fmaxf(mx0, fmaxf(sacc[nt][0], sacc[nt][1]));
            mx1 = fmaxf(mx1, fmaxf(sacc[nt][2], sacc[nt][3]));
        }
        mx0 = fmaxf(mx0, __shfl_xor_sync(0xffffffffu, mx0, 1));
        mx0 = fmaxf(mx0, __shfl_xor_sync(0xffffffffu, mx0, 2));
        mx1 = fmaxf(mx1, __shfl_xor_sync(0xffffffffu, mx1, 1));
        mx1 = fmaxf(mx1, __shfl_xor_sync(0xffffffffu, mx1, 2));
        float nm0 = fmaxf(m0, mx0), nm1 = fmaxf(m1, mx1);
        float f0 = __expf(m0 - nm0), f1 = __expf(m1 - nm1);
        float sum0 = 0.f, sum1 = 0.f;
#pragma unroll
        for (int nt = 0; nt < 8; nt++) {
            sacc[nt][0] = __expf(sacc[nt][0] - nm0);
            sacc[nt][1] = __expf(sacc[nt][1] - nm0);
            sacc[nt][2] = __expf(sacc[nt][2] - nm1);
            sacc[nt][3] = __expf(sacc[nt][3] - nm1);
            sum0 += sacc[nt][0] + sacc[nt][1];
            sum1 += sacc[nt][2] + sacc[nt][3];
        }
        sum0 += __shfl_xor_sync(0xffffffffu, sum0, 1);
        sum0 += __shfl_xor_sync(0xffffffffu, sum0, 2);
        sum1 += __shfl_xor_sync(0xffffffffu, sum1, 1);
        sum1 += __shfl_xor_sync(0xffffffffu, sum1, 2);
        l0 = l0 * f0 + sum0;
        l1 = l1 * f1 + sum1;
        m0 = nm0;
        m1 = nm1;
#pragma unroll
        for (int nt = 0; nt < 16; nt++) {
            oacc[nt][0] *= f0;
            oacc[nt][1] *= f0;
            oacc[nt][2] *= f1;
            oacc[nt][3] *= f1;
        }

        // ---- O += P V (fp16x2: (Ph + Pl) * Vh) ----
#pragma unroll
        for (int ks2 = 0; ks2 < 4; ks2++) {
            const float* ce = sacc[2 * ks2];
            const float* co = sacc[2 * ks2 + 1];
            uint32_t ph[4], pl[4];
            split2h(ce[0], ce[1], ph[0], pl[0]);
            split2h(ce[2], ce[3], ph[1], pl[1]);
            split2h(co[0], co[1], ph[2], pl[2]);
            split2h(co[2], co[3], ph[3], pl[3]);
            const uint32_t kc2 = (uint32_t)(ks2 * 16 + (lane >> 4) * 8);
            const uint32_t brow = (uint32_t)((lane & 7) + ((lane >> 3) & 1) * 8);
#pragma unroll
            for (int ng = 0; ng < 8; ng++) {
                uint32_t row = (uint32_t)(ng * 16) + brow;
                uint32_t rh[4];
                ldsm_x4(rh, stg + (OVH + row * LV + kc2) * 2);
                uint32_t b0[2] = {rh[0], rh[2]}, b1[2] = {rh[1], rh[3]};
                mma_f16(oacc[2 * ng],     ph, b0);
                mma_f16(oacc[2 * ng],     pl, b0);
                mma_f16(oacc[2 * ng + 1], ph, b1);
                mma_f16(oacc[2 * ng + 1], pl, b1);
            }
        }
        __syncthreads();
    }

    // ---- epilogue: normalize, store fp16 O in [b,s,h,d] ----
    const float inv0 = 1.f / l0, inv1 = 1.f / l1;
    const int row0 = q0 + wid * 16 + (lane >> 2);
#pragma unroll
    for (int nt = 0; nt < 16; nt++) {
        int col = nt * 8 + 2 * (lane & 3);
        size_t o0 = ((size_t)(b * S + row0) * H + h) * D + col;
        size_t o1 = ((size_t)(b * S + row0 + 8) * H + h) * D + col;
        *reinterpret_cast<__half2*>(Oh + o0) =
            __floats2half2_rn(oacc[nt][0] * inv0, oacc[nt][1] * inv0);
        *reinterpret_cast<__half2*>(Oh + o1) =
            __floats2half2_rn(oacc[nt][2] * inv1, oacc[nt][3] * inv1);
    }
}

// ---------------- host ----------------
extern "C" void kernel_launch(void* const* d_in, const int* in_sizes, int n_in,
                              void* d_out, int out_size)
{
    const float* x  = (const float*)d_in[0];
    const float* fc = (const float*)d_in[1];
    const float* wq = (const float*)d_in[2];
    const float* wk = (const float*)d_in[3];
    const float* wv = (const float*)d_in[4];
    const float* wo = (const float*)d_in[5];
    float* out = (float*)d_out;

    float *pq, *pk, *pv;
    cudaGetSymbolAddress((void**)&pq, g_q);
    cudaGetSymbolAddress((void**)&pk, g_k);
    cudaGetSymbolAddress((void**)&pv, g_v);
    __half *xa_h, *oa_h;
    __half *wqT_h, *wqT_l, *wkT_h, *wkT_l, *wvT_h, *wvT_l, *woT_h, *woT_l;
    __half *qs_h, *ks_h, *ks_l, *vt_h;
    cudaGetSymbolAddress((void**)&xa_h, g_xa_h);
    cudaGetSymbolAddress((void**)&oa_h, g_oa_h);
    cudaGetSymbolAddress((void**)&wqT_h, g_wqT_h);
    cudaGetSymbolAddress((void**)&wqT_l, g_wqT_l);
    cudaGetSymbolAddress((void**)&wkT_h, g_wkT_h);
    cudaGetSymbolAddress((void**)&wkT_l, g_wkT_l);
    cudaGetSymbolAddress((void**)&wvT_h, g_wvT_h);
    cudaGetSymbolAddress((void**)&wvT_l, g_wvT_l);
    cudaGetSymbolAddress((void**)&woT_h, g_woT_h);
    cudaGetSymbolAddress((void**)&woT_l, g_woT_l);
    cudaGetSymbolAddress((void**)&qs_h, g_qs_h);
    cudaGetSymbolAddress((void**)&ks_h, g_ks_h);
    cudaGetSymbolAddress((void**)&ks_l, g_ks_l);
    cudaGetSymbolAddress((void**)&vt_h, g_vt_h);

    cudaFuncSetAttribute(gemm_tc, cudaFuncAttributeMaxDynamicSharedMemorySize, GSM_BYTES);
    cudaFuncSetAttribute(attn_tc, cudaFuncAttributeMaxDynamicSharedMemorySize, ATT_SMEM);

    // x -> fp16
    {
        int n4 = MROWS * HID / 4;
        to_f16<<<(n4 + 255) / 256, 256>>>((const float4*)x, (__half2*)xa_h, n4);
    }
    // transpose + split weights (fp16 hi/lo)
    {
        dim3 blk(32, 8);
        transpose_split_h<<<dim3(ND_Q / 32, HID / 32), blk>>>(wq, wqT_h, wqT_l, HID, ND_Q);
        transpose_split_h<<<dim3(ND_KV / 32, HID / 32), blk>>>(wk, wkT_h, wkT_l, HID, ND_KV);
        transpose_split_h<<<dim3(ND_KV / 32, HID / 32), blk>>>(wv, wvT_h, wvT_l, HID, ND_KV);
        transpose_split_h<<<dim3(ND_Q / 32, ND_Q / 32), blk>>>(wo, woT_h, woT_l, ND_Q, HID);
    }
    // QKV projections (fp16x2 tensor cores)
    {
        gemm_tc<<<dim3(ND_Q / GBN, MROWS / GBM), 256, GSM_BYTES>>>(
            xa_h, wqT_h, wqT_l, pq, MROWS, ND_Q, HID);
        gemm_tc<<<dim3(ND_KV / GBN, MROWS / GBM), 256, GSM_BYTES>>>(
            xa_h, wkT_h, wkT_l, pk, MROWS, ND_KV, HID);
        gemm_tc<<<dim3(ND_KV / GBN, MROWS / GBM), 256, GSM_BYTES>>>(
            xa_h, wvT_h, wvT_l, pv, MROWS, ND_KV, HID);
    }
    // RoPE + relayout for attention (fp16)
    {
        int nq = B * H * S * (D / 2);
        rope_q_f16<<<(nq + 255) / 256, 256>>>(pq, fc, qs_h);
        int nk = B * KVH * S * (D / 2);
        rope_k_f16<<<(nk + 255) / 256, 256>>>(pk, fc, ks_h, ks_l);
        dim3 blk(32, 8);
        v_t_f16<<<dim3(D / 32, S / 32, B * KVH), blk>>>(pv, vt_h);
    }
    // tensor-core flash attention (fp16x2)
    {
        dim3 grid(S / AM, H, B);
        attn_tc<<<grid, 256, ATT_SMEM>>>(qs_h, ks_h, ks_l, vt_h, oa_h);
    }
    // output projection (fp16x2 tensor cores)
    {
        gemm_tc<<<dim3(HID / GBN, MROWS / GBM), 256, GSM_BYTES>>>(
            oa_h, woT_h, woT_l, out, MROWS, HID, ND_Q);
    }
}

// round 10
// speedup vs baseline: 5.6044x; 1.3549x over previous
#include <cuda_runtime.h>
#include <cuda_bf16.h>
#include <cuda_fp16.h>
#include <cstdint>

#define B 2
#define S 2048
#define HID 2048
#define H 16
#define KVH 4
#define D 128
#define GROUPS (H / KVH)
#define MROWS (B * S)          // 4096
#define ND_Q (H * D)           // 2048
#define ND_KV (KVH * D)        // 512
#define QK_SCALE 0.08838834764831845f

// ---------------- scratch (no allocations allowed) ----------------
__device__ float g_q[MROWS * H * D];
__device__ float g_k[MROWS * KVH * D];
__device__ float g_v[MROWS * KVH * D];

__device__ __align__(16) __half g_xa_h[MROWS * HID];      // x as fp16
__device__ __align__(16) __half g_oa_h[MROWS * ND_Q];     // attention out as fp16
__device__ __align__(16) __half g_wqT_h[ND_Q * HID];
__device__ __align__(16) __half g_wkT_h[ND_KV * HID];
__device__ __align__(16) __half g_wvT_h[ND_KV * HID];
__device__ __align__(16) __half g_woT_h[HID * ND_Q];
// attention operand layouts (fp16x2 path)
__device__ __align__(16) __half g_qs_h[B * H * S * D];    // [b][h][s][d], scaled
__device__ __align__(16) __half g_ks_h[B * KVH * S * D];  // [b][kvh][s][d]
__device__ __align__(16) __half g_ks_l[B * KVH * S * D];
__device__ __align__(16) __half g_vt_h[B * KVH * D * S];  // [b][kvh][d][s]

// ---------------- helpers ----------------
__device__ __forceinline__ uint32_t smem_u32(const void* p) {
    uint32_t a;
    asm("{ .reg .u64 t; cvta.to.shared.u64 t, %1; cvt.u32.u64 %0, t; }" : "=r"(a) : "l"(p));
    return a;
}
__device__ __forceinline__ void cp_async16(uint32_t saddr, const void* gaddr) {
    asm volatile("cp.async.cg.shared.global [%0], [%1], 16;" :: "r"(saddr), "l"(gaddr)
                 : "memory");
}
__device__ __forceinline__ void cp_commit() {
    asm volatile("cp.async.commit_group;" ::: "memory");
}
template <int N>
__device__ __forceinline__ void cp_wait() {
    asm volatile("cp.async.wait_group %0;" :: "n"(N) : "memory");
}
__device__ __forceinline__ void ldsm_x4(uint32_t* r, uint32_t addr) {
    asm volatile("ldmatrix.sync.aligned.m8n8.x4.shared.b16 {%0,%1,%2,%3}, [%4];"
                 : "=r"(r[0]), "=r"(r[1]), "=r"(r[2]), "=r"(r[3]) : "r"(addr));
}
__device__ __forceinline__ void mma_f16(float* c, const uint32_t* a, const uint32_t* b) {
    asm volatile(
        "mma.sync.aligned.m16n8k16.row.col.f32.f16.f16.f32 "
        "{%0,%1,%2,%3}, {%4,%5,%6,%7}, {%8,%9}, {%0,%1,%2,%3};"
        : "+f"(c[0]), "+f"(c[1]), "+f"(c[2]), "+f"(c[3])
        : "r"(a[0]), "r"(a[1]), "r"(a[2]), "r"(a[3]), "r"(b[0]), "r"(b[1]));
}
// fp32 pair -> fp16 (hi, lo) packed
__device__ __forceinline__ void split2h(float x, float y, uint32_t& hi, uint32_t& lo) {
    __half hx = __float2half_rn(x), hy = __float2half_rn(y);
    __half2 hh; hh.x = hx; hh.y = hy;
    __half2 ll;
    ll.x = __float2half_rn(x - __half2float(hx));
    ll.y = __float2half_rn(y - __half2float(hy));
    hi = *reinterpret_cast<uint32_t*>(&hh);
    lo = *reinterpret_cast<uint32_t*>(&ll);
}

// ---------------- fp32 -> fp16 convert ----------------
__global__ void to_f16(const float4* __restrict__ src, __half2* __restrict__ dst, int n4) {
    int i = blockIdx.x * blockDim.x + threadIdx.x;
    if (i >= n4) return;
    float4 v = src[i];
    dst[2 * i]     = __floats2half2_rn(v.x, v.y);
    dst[2 * i + 1] = __floats2half2_rn(v.z, v.w);
}

// ---------------- transpose: W[K,N] fp32 -> T[N,K] fp16 ----------------
__global__ void transpose_h(const float* __restrict__ W, __half* __restrict__ Th,
                            int K, int N) {
    __shared__ float t[32][33];
    int k0 = blockIdx.y * 32, n0 = blockIdx.x * 32;
    int tx = threadIdx.x, ty = threadIdx.y;
#pragma unroll
    for (int j = 0; j < 4; j++)
        t[ty + j * 8][tx] = W[(size_t)(k0 + ty + j * 8) * N + n0 + tx];
    __syncthreads();
#pragma unroll
    for (int j = 0; j < 4; j++) {
        int n = n0 + ty + j * 8;
        Th[(size_t)n * K + k0 + tx] = __float2half_rn(t[tx][ty + j * 8]);
    }
}

// ---------------- fp16 tensor-core GEMM: C = A @ Th^T ----------------
#define GBM 128
#define GBN 128
#define GBK 32
#define LDT 40
#define TILE_E (GBM * LDT)
#define STAGE_E (2 * TILE_E)          // A, B
#define GSM_BYTES (2 * STAGE_E * 2)   // 40960

__global__ __launch_bounds__(256, 1)
void gemm_tc(const __half* __restrict__ A, const __half* __restrict__ Bh,
             float* __restrict__ C, int M, int N, int K)
{
    extern __shared__ __half sm[];
    const uint32_t sb = smem_u32(sm);
    const int tid = threadIdx.x;
    const int wid = tid / 32, lane = tid % 32;
    const int warp_m = wid % 4;
    const int warp_n = wid / 4;
    const int m0 = blockIdx.y * GBM, n0 = blockIdx.x * GBN;

    const int ld_row = tid / 4;
    const int ld_col = (tid % 4) * 8;

    const __half* pA  = A  + (size_t)(m0 + ld_row) * K + ld_col;
    const __half* pBh = Bh + (size_t)(n0 + ld_row) * K + ld_col;
    const size_t rstep64 = (size_t)64 * K;

    auto load_chunk = [&](int t, int stg) {
        uint32_t sbase = sb + (uint32_t)(stg * STAGE_E) * 2u;
        uint32_t soff = ((uint32_t)ld_row * LDT + (uint32_t)ld_col) * 2u;
        const int kk = t * GBK;
#pragma unroll
        for (int j = 0; j < 2; j++) {
            uint32_t so = soff + (uint32_t)(j * 64 * LDT) * 2u;
            cp_async16(sbase + 0 * TILE_E * 2 + so, pA  + kk + j * rstep64);
            cp_async16(sbase + 1 * TILE_E * 2 + so, pBh + kk + j * rstep64);
        }
    };

    float acc[2][8][4];
#pragma unroll
    for (int i = 0; i < 2; i++)
#pragma unroll
        for (int j = 0; j < 8; j++)
#pragma unroll
            for (int r = 0; r < 4; r++) acc[i][j][r] = 0.f;

    const int nch = K / GBK;
    load_chunk(0, 0);
    cp_commit();

    for (int t = 0; t < nch; t++) {
        const int stg = t & 1;
        if (t + 1 < nch) {
            load_chunk(t + 1, stg ^ 1);
            cp_commit();
            cp_wait<1>();
        } else {
            cp_wait<0>();
        }
        __syncthreads();

        const uint32_t sbase = sb + (uint32_t)(stg * STAGE_E) * 2u;
#pragma unroll
        for (int ks = 0; ks < 2; ks++) {
            const uint32_t kc = (uint32_t)(ks * 16 + (lane / 16) * 8);
            uint32_t ah[2][4];
#pragma unroll
            for (int mt = 0; mt < 2; mt++) {
                uint32_t row = (uint32_t)(warp_m * 32 + mt * 16 + (lane % 16));
                uint32_t off = (row * LDT + kc) * 2u;
                ldsm_x4(ah[mt], sbase + 0 * TILE_E * 2 + off);
            }
            uint32_t bh[8][2];
#pragma unroll
            for (int ng = 0; ng < 4; ng++) {
                uint32_t row = (uint32_t)(warp_n * 64 + ng * 16 + (lane % 8) +
                                          ((lane / 8) % 2) * 8);
                uint32_t off = (row * LDT + kc) * 2u;
                uint32_t r[4];
                ldsm_x4(r, sbase + 1 * TILE_E * 2 + off);
                bh[2 * ng][0] = r[0]; bh[2 * ng][1] = r[2];
                bh[2 * ng + 1][0] = r[1]; bh[2 * ng + 1][1] = r[3];
            }
#pragma unroll
            for (int mt = 0; mt < 2; mt++)
#pragma unroll
                for (int nt = 0; nt < 8; nt++)
                    mma_f16(acc[mt][nt], ah[mt], bh[nt]);
        }
        __syncthreads();
    }

#pragma unroll
    for (int mt = 0; mt < 2; mt++) {
        int row = m0 + warp_m * 32 + mt * 16 + lane / 4;
#pragma unroll
        for (int nt = 0; nt < 8; nt++) {
            int col = n0 + warp_n * 64 + nt * 8 + (lane % 4) * 2;
            float2 v0 = make_float2(acc[mt][nt][0], acc[mt][nt][1]);
            float2 v1 = make_float2(acc[mt][nt][2], acc[mt][nt][3]);
            *reinterpret_cast<float2*>(&C[(size_t)row * N + col]) = v0;
            *reinterpret_cast<float2*>(&C[(size_t)(row + 8) * N + col]) = v1;
        }
    }
}

// -------- RoPE + scale, Q: [b,s,h,d] f32 -> [b,h,s,d] fp16 --------
__global__ void rope_q_f16(const float* __restrict__ q, const float* __restrict__ fc,
                           __half* __restrict__ qh) {
    int idx = blockIdx.x * blockDim.x + threadIdx.x;
    if (idx >= B * H * S * (D / 2)) return;
    int i = idx % (D / 2);
    int s = (idx / (D / 2)) % S;
    int h = (idx / (D / 2) / S) % H;
    int b = idx / (D / 2) / S / H;
    float c  = fc[(s * (D / 2) + i) * 2 + 0];
    float sn = fc[(s * (D / 2) + i) * 2 + 1];
    const float* p = q + ((size_t)(b * S + s) * H + h) * D + 2 * i;
    float x0 = p[0], x1 = p[1];
    float r0 = (x0 * c - x1 * sn) * QK_SCALE;
    float r1 = (x0 * sn + x1 * c) * QK_SCALE;
    size_t o = ((size_t)(b * H + h) * S + s) * D + 2 * i;
    *reinterpret_cast<__half2*>(qh + o) = __floats2half2_rn(r0, r1);
}

// -------- RoPE + split, K: [b,s,kvh,d] f32 -> [b,kvh,s,d] fp16 hi/lo --------
__global__ void rope_k_f16(const float* __restrict__ k, const float* __restrict__ fc,
                           __half* __restrict__ kh, __half* __restrict__ kl) {
    int idx = blockIdx.x * blockDim.x + threadIdx.x;
    if (idx >= B * KVH * S * (D / 2)) return;
    int i = idx % (D / 2);
    int s = (idx / (D / 2)) % S;
    int h = (idx / (D / 2) / S) % KVH;
    int b = idx / (D / 2) / S / KVH;
    float c  = fc[(s * (D / 2) + i) * 2 + 0];
    float sn = fc[(s * (D / 2) + i) * 2 + 1];
    const float* p = k + ((size_t)(b * S + s) * KVH + h) * D + 2 * i;
    float x0 = p[0], x1 = p[1];
    float r0 = x0 * c - x1 * sn;
    float r1 = x0 * sn + x1 * c;
    __half h0 = __float2half_rn(r0), h1 = __float2half_rn(r1);
    size_t o = ((size_t)(b * KVH + h) * S + s) * D + 2 * i;
    __half2 hh; hh.x = h0; hh.y = h1;
    *reinterpret_cast<__half2*>(kh + o) = hh;
    *reinterpret_cast<__half2*>(kl + o) =
        __floats2half2_rn(r0 - __half2float(h0), r1 - __half2float(h1));
}

// -------- V transpose: [b,s,kvh,d] f32 -> [b,kvh,d,s] fp16 --------
__global__ void v_t_f16(const float* __restrict__ v, __half* __restrict__ vh) {
    __shared__ float t[32][33];
    int d0 = blockIdx.x * 32, s0 = blockIdx.y * 32;
    int bk = blockIdx.z;
    int b = bk / KVH, kvh = bk % KVH;
    int tx = threadIdx.x, ty = threadIdx.y;
#pragma unroll
    for (int j = 0; j < 4; j++)
        t[ty + j * 8][tx] = v[((size_t)(b * S + s0 + ty + j * 8) * KVH + kvh) * D + d0 + tx];
    __syncthreads();
#pragma unroll
    for (int j = 0; j < 4; j++) {
        int d = d0 + ty + j * 8;
        size_t o = ((size_t)(b * KVH + kvh) * D + d) * S + s0 + tx;
        vh[o] = __float2half_rn(t[tx][ty + j * 8]);
    }
}

// ---------------- tensor-core flash attention (fp16x2), causal, GQA ----------------
#define AM 128
#define AN 64
#define LQ 136
#define LV 72
#define SQH 0
#define SST 17408                 // start of KV stages (after Q)
#define STSZ 26624                // KH 8704 + KL 8704 + VH 9216
#define OKL 8704
#define OVH 17408
#define ATT_SMEM ((SST + 2 * STSZ) * 2)   // 141312 bytes

__global__ __launch_bounds__(256, 1)
void attn_tc(const __half* __restrict__ Qh,
             const __half* __restrict__ Kh, const __half* __restrict__ Kl,
             const __half* __restrict__ Vh,
             __half* __restrict__ Oh)
{
    extern __shared__ __half sma[];
    const uint32_t sb = smem_u32(sma);
    const int tid = threadIdx.x, wid = tid / 32, lane = tid % 32;
    const int bx = blockIdx.x, h = blockIdx.y, b = blockIdx.z;
    const int kvh = h / GROUPS;
    const int q0 = bx * AM;

    const __half* qhp = Qh + ((size_t)(b * H + h) * S + q0) * D;
    const __half* khp = Kh + (size_t)(b * KVH + kvh) * S * D;
    const __half* klp = Kl + (size_t)(b * KVH + kvh) * S * D;
    const __half* vhp = Vh + (size_t)(b * KVH + kvh) * D * S;

#pragma unroll
    for (int j = 0; j < 8; j++) {
        int seg = tid + j * 256;
        int row = seg >> 4, c = (seg & 15) * 8;
        cp_async16(sb + (uint32_t)(SQH + row * LQ + c) * 2, qhp + (size_t)row * D + c);
    }
    cp_commit();

    auto load_kv = [&](int t, int stg) {
        uint32_t sbase = sb + (uint32_t)(SST + stg * STSZ) * 2;
        int kv0 = t * AN;
#pragma unroll
        for (int j = 0; j < 4; j++) {
            int seg = tid + j * 256;
            int row = seg >> 4, c = (seg & 15) * 8;
            cp_async16(sbase + (uint32_t)(row * LQ + c) * 2,
                       khp + (size_t)(kv0 + row) * D + c);
            cp_async16(sbase + (uint32_t)(OKL + row * LQ + c) * 2,
                       klp + (size_t)(kv0 + row) * D + c);
        }
#pragma unroll
        for (int j = 0; j < 4; j++) {
            int seg = tid + j * 256;
            int row = seg >> 3, c = (seg & 7) * 8;
            cp_async16(sbase + (uint32_t)(OVH + row * LV + c) * 2,
                       vhp + (size_t)row * S + kv0 + c);
        }
    };

    float m0 = -1e30f, m1 = -1e30f, l0 = 0.f, l1 = 0.f;
    float oacc[16][4];
#pragma unroll
    for (int i = 0; i < 16; i++)
#pragma unroll
        for (int j = 0; j < 4; j++) oacc[i][j] = 0.f;

    const int ntiles = 2 * (bx + 1);
    load_kv(0, 0);
    cp_commit();

    for (int t = 0; t < ntiles; t++) {
        if (t + 1 < ntiles) {
            load_kv(t + 1, (t + 1) & 1);
            cp_commit();
            cp_wait<1>();
        } else {
            cp_wait<0>();
        }
        __syncthreads();
        const uint32_t stg = sb + (uint32_t)(SST + (t & 1) * STSZ) * 2;

        // ---- S = Q K^T (fp16x2: Qh * (Kh + Kl)) ----
        float sacc[8][4];
#pragma unroll
        for (int i = 0; i < 8; i++)
#pragma unroll
            for (int j = 0; j < 4; j++) sacc[i][j] = 0.f;

#pragma unroll
        for (int ks = 0; ks < 8; ks++) {
            const uint32_t kc = (uint32_t)(ks * 16 + (lane >> 4) * 8);
            uint32_t ah[4];
            const uint32_t qrow = (uint32_t)(wid * 16 + (lane & 15));
            ldsm_x4(ah, sb + (SQH + qrow * LQ + kc) * 2);
            const uint32_t brow = (uint32_t)((lane & 7) + ((lane >> 3) & 1) * 8);
#pragma unroll
            for (int ng = 0; ng < 4; ng++) {
                uint32_t row = (uint32_t)(ng * 16) + brow;
                uint32_t rh[4], rl[4];
                ldsm_x4(rh, stg + (row * LQ + kc) * 2);
                ldsm_x4(rl, stg + (OKL + row * LQ + kc) * 2);
                uint32_t b0[2] = {rh[0], rh[2]}, b1[2] = {rh[1], rh[3]};
                uint32_t bl0[2] = {rl[0], rl[2]}, bl1[2] = {rl[1], rl[3]};
                mma_f16(sacc[2 * ng],     ah, b0);
                mma_f16(sacc[2 * ng],     ah, bl0);
                mma_f16(sacc[2 * ng + 1], ah, b1);
                mma_f16(sacc[2 * ng + 1], ah, bl1);
            }
        }

        // ---- causal mask (only diagonal tiles) ----
        const int row0 = q0 + wid * 16 + (lane >> 2);
        if (t >= 2 * bx) {
            const int kvb = t * AN + 2 * (lane & 3);
#pragma unroll
            for (int nt = 0; nt < 8; nt++) {
                int col = kvb + nt * 8;
                if (col     > row0)     sacc[nt][0] = -1e30f;
                if (col + 1 > row0)     sacc[nt][1] = -1e30f;
                if (col     > row0 + 8) sacc[nt][2] = -1e30f;
                if (col + 1 > row0 + 8) sacc[nt][3] = -1e30f;
            }
        }

        // ---- online softmax ----
        float mx0 = -1e30f, mx1 = -1e30f;
#pragma unroll
        for (int nt = 0; nt < 8; nt++) {
            mx0 = fmaxf(mx0, fmaxf(sacc[nt][0], sacc[nt][1]));
            mx1 = fmaxf(mx1, fmaxf(sacc[nt][2], sacc[nt][3]));
        }
        mx0 = fmaxf(mx0, __shfl_xor_sync(0xffffffffu, mx0, 1));
        mx0 = fmaxf(mx0, __shfl_xor_sync(0xffffffffu, mx0, 2));
        mx1 = fmaxf(mx1, __shfl_xor_sync(0xffffffffu, mx1, 1));
        mx1 = fmaxf(mx1, __shfl_xor_sync(0xffffffffu, mx1, 2));
        float nm0 = fmaxf(m0, mx0), nm1 = fmaxf(m1, mx1);
        float f0 = __expf(m0 - nm0), f1 = __expf(m1 - nm1);
        float sum0 = 0.f, sum1 = 0.f;
#pragma unroll
        for (int nt = 0; nt < 8; nt++) {
            sacc[nt][0] = __expf(sacc[nt][0] - nm0);
            sacc[nt][1] = __expf(sacc[nt][1] - nm0);
            sacc[nt][2] = __expf(sacc[nt][2] - nm1);
            sacc[nt][3] = __expf(sacc[nt][3] - nm1);
            sum0 += sacc[nt][0] + sacc[nt][1];
            sum1 += sacc[nt][2] + sacc[nt][3];
        }
        sum0 += __shfl_xor_sync(0xffffffffu, sum0, 1);
        sum0 += __shfl_xor_sync(0xffffffffu, sum0, 2);
        sum1 += __shfl_xor_sync(0xffffffffu, sum1, 1);
        sum1 += __shfl_xor_sync(0xffffffffu, sum1, 2);
        l0 = l0 * f0 + sum0;
        l1 = l1 * f1 + sum1;
        m0 = nm0;
        m1 = nm1;
#pragma unroll
        for (int nt = 0; nt < 16; nt++) {
            oacc[nt][0] *= f0;
            oacc[nt][1] *= f0;
            oacc[nt][2] *= f1;
            oacc[nt][3] *= f1;
        }

        // ---- O += P V (fp16x2: (Ph + Pl) * Vh) ----
#pragma unroll
        for (int ks2 = 0; ks2 < 4; ks2++) {
            const float* ce = sacc[2 * ks2];
            const float* co = sacc[2 * ks2 + 1];
            uint32_t ph[4], pl[4];
            split2h(ce[0], ce[1], ph[0], pl[0]);
            split2h(ce[2], ce[3], ph[1], pl[1]);
            split2h(co[0], co[1], ph[2], pl[2]);
            split2h(co[2], co[3], ph[3], pl[3]);
            const uint32_t kc2 = (uint32_t)(ks2 * 16 + (lane >> 4) * 8);
            const uint32_t brow = (uint32_t)((lane & 7) + ((lane >> 3) & 1) * 8);
#pragma unroll
            for (int ng = 0; ng < 8; ng++) {
                uint32_t row = (uint32_t)(ng * 16) + brow;
                uint32_t rh[4];
                ldsm_x4(rh, stg + (OVH + row * LV + kc2) * 2);
                uint32_t b0[2] = {rh[0], rh[2]}, b1[2] = {rh[1], rh[3]};
                mma_f16(oacc[2 * ng],     ph, b0);
                mma_f16(oacc[2 * ng],     pl, b0);
                mma_f16(oacc[2 * ng + 1], ph, b1);
                mma_f16(oacc[2 * ng + 1], pl, b1);
            }
        }
        __syncthreads();
    }

    // ---- epilogue: normalize, store fp16 O in [b,s,h,d] ----
    const float inv0 = 1.f / l0, inv1 = 1.f / l1;
    const int row0 = q0 + wid * 16 + (lane >> 2);
#pragma unroll
    for (int nt = 0; nt < 16; nt++) {
        int col = nt * 8 + 2 * (lane & 3);
        size_t o0 = ((size_t)(b * S + row0) * H + h) * D + col;
        size_t o1 = ((size_t)(b * S + row0 + 8) * H + h) * D + col;
        *reinterpret_cast<__half2*>(Oh + o0) =
            __floats2half2_rn(oacc[nt][0] * inv0, oacc[nt][1] * inv0);
        *reinterpret_cast<__half2*>(Oh + o1) =
            __floats2half2_rn(oacc[nt][2] * inv1, oacc[nt][3] * inv1);
    }
}

// ---------------- host ----------------
extern "C" void kernel_launch(void* const* d_in, const int* in_sizes, int n_in,
                              void* d_out, int out_size)
{
    const float* x  = (const float*)d_in[0];
    const float* fc = (const float*)d_in[1];
    const float* wq = (const float*)d_in[2];
    const float* wk = (const float*)d_in[3];
    const float* wv = (const float*)d_in[4];
    const float* wo = (const float*)d_in[5];
    float* out = (float*)d_out;

    float *pq, *pk, *pv;
    cudaGetSymbolAddress((void**)&pq, g_q);
    cudaGetSymbolAddress((void**)&pk, g_k);
    cudaGetSymbolAddress((void**)&pv, g_v);
    __half *xa_h, *oa_h;
    __half *wqT_h, *wkT_h, *wvT_h, *woT_h;
    __half *qs_h, *ks_h, *ks_l, *vt_h;
    cudaGetSymbolAddress((void**)&xa_h, g_xa_h);
    cudaGetSymbolAddress((void**)&oa_h, g_oa_h);
    cudaGetSymbolAddress((void**)&wqT_h, g_wqT_h);
    cudaGetSymbolAddress((void**)&wkT_h, g_wkT_h);
    cudaGetSymbolAddress((void**)&wvT_h, g_wvT_h);
    cudaGetSymbolAddress((void**)&woT_h, g_woT_h);
    cudaGetSymbolAddress((void**)&qs_h, g_qs_h);
    cudaGetSymbolAddress((void**)&ks_h, g_ks_h);
    cudaGetSymbolAddress((void**)&ks_l, g_ks_l);
    cudaGetSymbolAddress((void**)&vt_h, g_vt_h);

    cudaFuncSetAttribute(gemm_tc, cudaFuncAttributeMaxDynamicSharedMemorySize, GSM_BYTES);
    cudaFuncSetAttribute(attn_tc, cudaFuncAttributeMaxDynamicSharedMemorySize, ATT_SMEM);

    // x -> fp16
    {
        int n4 = MROWS * HID / 4;
        to_f16<<<(n4 + 255) / 256, 256>>>((const float4*)x, (__half2*)xa_h, n4);
    }
    // transpose weights (fp16)
    {
        dim3 blk(32, 8);
        transpose_h<<<dim3(ND_Q / 32, HID / 32), blk>>>(wq, wqT_h, HID, ND_Q);
        transpose_h<<<dim3(ND_KV / 32, HID / 32), blk>>>(wk, wkT_h, HID, ND_KV);
        transpose_h<<<dim3(ND_KV / 32, HID / 32), blk>>>(wv, wvT_h, HID, ND_KV);
        transpose_h<<<dim3(ND_Q / 32, ND_Q / 32), blk>>>(wo, woT_h, ND_Q, HID);
    }
    // QKV projections (fp16 tensor cores)
    {
        gemm_tc<<<dim3(ND_Q / GBN, MROWS / GBM), 256, GSM_BYTES>>>(
            xa_h, wqT_h, pq, MROWS, ND_Q, HID);
        gemm_tc<<<dim3(ND_KV / GBN, MROWS / GBM), 256, GSM_BYTES>>>(
            xa_h, wkT_h, pk, MROWS, ND_KV, HID);
        gemm_tc<<<dim3(ND_KV / GBN, MROWS / GBM), 256, GSM_BYTES>>>(
            xa_h, wvT_h, pv, MROWS, ND_KV, HID);
    }
    // RoPE + relayout for attention (fp16)
    {
        int nq = B * H * S * (D / 2);
        rope_q_f16<<<(nq + 255) / 256, 256>>>(pq, fc, qs_h);
        int nk = B * KVH * S * (D / 2);
        rope_k_f16<<<(nk + 255) / 256, 256>>>(pk, fc, ks_h, ks_l);
        dim3 blk(32, 8);
        v_t_f16<<<dim3(D / 32, S / 32, B * KVH), blk>>>(pv, vt_h);
    }
    // tensor-core flash attention (fp16x2)
    {
        dim3 grid(S / AM, H, B);
        attn_tc<<<grid, 256, ATT_SMEM>>>(qs_h, ks_h, ks_l, vt_h, oa_h);
    }
    // output projection (fp16 tensor cores)
    {
        gemm_tc<<<dim3(HID / GBN, MROWS / GBM), 256, GSM_BYTES>>>(
            oa_h, woT_h, out, MROWS, HID, ND_Q);
    }
}